// round 1
// baseline (speedup 1.0000x reference)
#include <cuda_runtime.h>
#include <cstdint>

// ---------------- problem constants ----------------
#define B_  4
#define S_  2048
#define D_  1024
#define P_  256
#define H_  16
#define DH_ 64
#define DFF_ 512
#define M_  (B_*S_)           // 8192 rows
#define EPS_ 1e-6f

// ---------------- scratch (static device globals; no allocation) ----------------
__device__ float g_xn [M_*D_];
__device__ float g_q  [M_*D_];
__device__ float g_k  [M_*D_];
__device__ float g_v  [M_*D_];
__device__ float g_ctx[M_*D_];
__device__ float g_x2 [M_*D_];
__device__ float g_h  [M_*DFF_];

// ---------------- LayerNorm (torch semantics: unbiased std, eps on std) ----------------
__global__ void ln_kernel(const float* __restrict__ in,
                          const float* __restrict__ alpha,
                          const float* __restrict__ beta,
                          float* __restrict__ out) {
    const int row = blockIdx.x;
    const int t = threadIdx.x;            // 256 threads, 4 elems each
    const float* x = in + (size_t)row * D_;
    float v[4];
    float s = 0.f;
    #pragma unroll
    for (int i = 0; i < 4; i++) { v[i] = x[t + 256*i]; s += v[i]; }

    __shared__ float red[8];
    #pragma unroll
    for (int o = 16; o > 0; o >>= 1) s += __shfl_xor_sync(0xffffffffu, s, o);
    if ((t & 31) == 0) red[t >> 5] = s;
    __syncthreads();
    float tot = 0.f;
    #pragma unroll
    for (int i = 0; i < 8; i++) tot += red[i];
    const float mu = tot * (1.0f / D_);

    float ss = 0.f;
    #pragma unroll
    for (int i = 0; i < 4; i++) { float d = v[i] - mu; ss += d * d; }
    __syncthreads();
    #pragma unroll
    for (int o = 16; o > 0; o >>= 1) ss += __shfl_xor_sync(0xffffffffu, ss, o);
    if ((t & 31) == 0) red[t >> 5] = ss;
    __syncthreads();
    float sst = 0.f;
    #pragma unroll
    for (int i = 0; i < 8; i++) sst += red[i];

    const float stdv = sqrtf(fmaxf(sst, 0.f) * (1.0f / (D_ - 1)));
    const float inv = 1.0f / (stdv + EPS_);
    float* o = out + (size_t)row * D_;
    #pragma unroll
    for (int i = 0; i < 4; i++) {
        int c = t + 256*i;
        o[c] = alpha[c] * (v[i] - mu) * inv + beta[c];
    }
}

// ---------------- SGEMM 128x128x8, 256 thr, 8x8 per thread ----------------
template<bool RELU, bool HASBIAS, bool HASRES>
__global__ void sgemm_kernel(const float* __restrict__ A, const float* __restrict__ Bm,
                             const float* __restrict__ bias, const float* __restrict__ res,
                             float* __restrict__ C, int M, int N, int K) {
    __shared__ float As[8][128];
    __shared__ float Bs[8][128];
    const int t  = threadIdx.x;
    const int tx = t & 15, ty = t >> 4;
    const int bx = blockIdx.x, by = blockIdx.y;

    const float* Ab = A  + (size_t)by * 128 * K;
    const float* Bb = Bm + (size_t)bx * 128;

    const int arow = t >> 1, acol = (t & 1) * 4;   // 128x8 A tile
    const int brow = t >> 5, bcol = (t & 31) * 4;  // 8x128  B tile

    float acc[8][8];
    #pragma unroll
    for (int i = 0; i < 8; i++)
        #pragma unroll
        for (int j = 0; j < 8; j++) acc[i][j] = 0.f;

    for (int k0 = 0; k0 < K; k0 += 8) {
        float4 a4 = *(const float4*)(Ab + (size_t)arow * K + k0 + acol);
        float4 b4 = *(const float4*)(Bb + (size_t)(k0 + brow) * N + bcol);
        As[acol+0][arow] = a4.x; As[acol+1][arow] = a4.y;
        As[acol+2][arow] = a4.z; As[acol+3][arow] = a4.w;
        *(float4*)&Bs[brow][bcol] = b4;
        __syncthreads();
        #pragma unroll
        for (int kk = 0; kk < 8; kk++) {
            float ar[8], br[8];
            #pragma unroll
            for (int i = 0; i < 8; i++) ar[i] = As[kk][ty*8 + i];
            #pragma unroll
            for (int j = 0; j < 8; j++) br[j] = Bs[kk][tx*8 + j];
            #pragma unroll
            for (int i = 0; i < 8; i++)
                #pragma unroll
                for (int j = 0; j < 8; j++) acc[i][j] += ar[i] * br[j];
        }
        __syncthreads();
    }

    #pragma unroll
    for (int i = 0; i < 8; i++) {
        const size_t row = (size_t)by * 128 + ty*8 + i;
        #pragma unroll
        for (int j = 0; j < 8; j++) {
            const int col = bx * 128 + tx*8 + j;
            float v = acc[i][j];
            if (HASBIAS) v += bias[col];
            if (HASRES)  v += res[row * N + col];
            if (RELU)    v = fmaxf(v, 0.f);
            C[row * N + col] = v;
        }
    }
}

// ---------------- fused attention (flash-style, fp32) ----------------
#define LDP 65
__global__ void attn_kernel(const float* __restrict__ Q, const float* __restrict__ K,
                            const float* __restrict__ V, float* __restrict__ O) {
    extern __shared__ float sm[];
    float* Qs = sm;                 // 64*65
    float* Ks = Qs + 64*LDP;
    float* Vs = Ks + 64*LDP;
    float* Ps = Vs + 64*LDP;

    const int qt = blockIdx.x, h = blockIdx.y, b = blockIdx.z;
    const int t = threadIdx.x;
    const int cg = t & 15, rg = t >> 4;
    const int r0 = rg * 4, c0 = cg * 4;

    for (int e = t; e < 64*64; e += 256) {
        int row = e >> 6, d = e & 63;
        Qs[row*LDP + d] = Q[((size_t)(b*S_ + qt*64 + row)) * D_ + h*DH_ + d];
    }
    __syncthreads();

    float m[4], l[4], o[4][4];
    #pragma unroll
    for (int i = 0; i < 4; i++) {
        m[i] = -1e30f; l[i] = 0.f;
        #pragma unroll
        for (int j = 0; j < 4; j++) o[i][j] = 0.f;
    }

    for (int kt = 0; kt < S_/64; kt++) {
        for (int e = t; e < 64*64; e += 256) {
            int row = e >> 6, d = e & 63;
            size_t g = ((size_t)(b*S_ + kt*64 + row)) * D_ + h*DH_ + d;
            Ks[row*LDP + d] = K[g];
            Vs[row*LDP + d] = V[g];
        }
        __syncthreads();

        float acc[4][4];
        #pragma unroll
        for (int i = 0; i < 4; i++)
            #pragma unroll
            for (int j = 0; j < 4; j++) acc[i][j] = 0.f;
        #pragma unroll 8
        for (int kk = 0; kk < 64; kk++) {
            float qv[4], kv[4];
            #pragma unroll
            for (int i = 0; i < 4; i++) qv[i] = Qs[(r0+i)*LDP + kk];
            #pragma unroll
            for (int j = 0; j < 4; j++) kv[j] = Ks[(c0+j)*LDP + kk];
            #pragma unroll
            for (int i = 0; i < 4; i++)
                #pragma unroll
                for (int j = 0; j < 4; j++) acc[i][j] += qv[i] * kv[j];
        }

        #pragma unroll
        for (int i = 0; i < 4; i++) {
            float tm = acc[i][0];
            #pragma unroll
            for (int j = 1; j < 4; j++) tm = fmaxf(tm, acc[i][j]);
            tm *= 0.125f;
            #pragma unroll
            for (int off = 1; off < 16; off <<= 1)
                tm = fmaxf(tm, __shfl_xor_sync(0xffffffffu, tm, off));
            const float mn = fmaxf(m[i], tm);
            const float corr = expf(m[i] - mn);
            float ts = 0.f;
            #pragma unroll
            for (int j = 0; j < 4; j++) {
                acc[i][j] = expf(acc[i][j] * 0.125f - mn);
                ts += acc[i][j];
            }
            #pragma unroll
            for (int off = 1; off < 16; off <<= 1)
                ts += __shfl_xor_sync(0xffffffffu, ts, off);
            l[i] = l[i] * corr + ts;
            m[i] = mn;
            #pragma unroll
            for (int j = 0; j < 4; j++) o[i][j] *= corr;
            #pragma unroll
            for (int j = 0; j < 4; j++) Ps[(r0+i)*LDP + c0 + j] = acc[i][j];
        }
        __syncthreads();

        #pragma unroll 8
        for (int k = 0; k < 64; k++) {
            float pv[4], vv[4];
            #pragma unroll
            for (int i = 0; i < 4; i++) pv[i] = Ps[(r0+i)*LDP + k];
            #pragma unroll
            for (int j = 0; j < 4; j++) vv[j] = Vs[k*LDP + c0 + j];
            #pragma unroll
            for (int i = 0; i < 4; i++)
                #pragma unroll
                for (int j = 0; j < 4; j++) o[i][j] += pv[i] * vv[j];
        }
        __syncthreads();
    }

    #pragma unroll
    for (int i = 0; i < 4; i++) {
        const float invl = 1.0f / l[i];
        float4 w;
        w.x = o[i][0]*invl; w.y = o[i][1]*invl; w.z = o[i][2]*invl; w.w = o[i][3]*invl;
        *(float4*)&O[((size_t)(b*S_ + qt*64 + r0 + i)) * D_ + h*DH_ + c0] = w;
    }
}

// ---------------- host launcher ----------------
extern "C" void kernel_launch(void* const* d_in, const int* in_sizes, int n_in,
                              void* d_out, int out_size) {
    const float* fx  = (const float*)d_in[0];
    const float* px  = (const float*)d_in[1];
    const float* Wq  = (const float*)d_in[2];
    const float* bq  = (const float*)d_in[3];
    const float* Wk  = (const float*)d_in[4];
    const float* bk  = (const float*)d_in[5];
    const float* Wv  = (const float*)d_in[6];
    const float* bv  = (const float*)d_in[7];
    const float* Wo  = (const float*)d_in[8];
    const float* bo  = (const float*)d_in[9];
    const float* a1  = (const float*)d_in[10];
    const float* be1 = (const float*)d_in[11];
    const float* a2  = (const float*)d_in[12];
    const float* be2 = (const float*)d_in[13];
    const float* W1  = (const float*)d_in[14];
    const float* b1  = (const float*)d_in[15];
    const float* W2  = (const float*)d_in[16];
    const float* b2  = (const float*)d_in[17];
    const float* Wp  = (const float*)d_in[18];
    const float* bp  = (const float*)d_in[19];

    float* xo = (float*)d_out;                    // x: M_ x D_
    float* po = xo + (size_t)M_ * D_;             // p: M_ x P_

    float *xn, *q, *k, *v, *ctx, *x2, *hb;
    cudaGetSymbolAddress((void**)&xn,  g_xn);
    cudaGetSymbolAddress((void**)&q,   g_q);
    cudaGetSymbolAddress((void**)&k,   g_k);
    cudaGetSymbolAddress((void**)&v,   g_v);
    cudaGetSymbolAddress((void**)&ctx, g_ctx);
    cudaGetSymbolAddress((void**)&x2,  g_x2);
    cudaGetSymbolAddress((void**)&hb,  g_h);

    const int smem_attn = 4 * 64 * LDP * sizeof(float);   // 66560 B
    cudaFuncSetAttribute(attn_kernel, cudaFuncAttributeMaxDynamicSharedMemorySize, smem_attn);

    // 1. xn = LN1(feature_x)
    ln_kernel<<<M_, 256>>>(fx, a1, be1, xn);

    // 2. Q,K,V
    dim3 gQKV(D_/128, M_/128);
    sgemm_kernel<false,true,false><<<gQKV, 256>>>(xn, Wq, bq, nullptr, q, M_, D_, D_);
    sgemm_kernel<false,true,false><<<gQKV, 256>>>(xn, Wk, bk, nullptr, k, M_, D_, D_);
    sgemm_kernel<false,true,false><<<gQKV, 256>>>(xn, Wv, bv, nullptr, v, M_, D_, D_);

    // 3. attention -> ctx
    attn_kernel<<<dim3(S_/64, H_, B_), 256, smem_attn>>>(q, k, v, ctx);

    // 4. x = xn + ctx@Wo + bo
    sgemm_kernel<false,true,true><<<gQKV, 256>>>(ctx, Wo, bo, xn, xo, M_, D_, D_);

    // 5. x2 = LN2(x)
    ln_kernel<<<M_, 256>>>(xo, a2, be2, x2);

    // 6. h = relu(x2@W1+b1); x = x + h@W2 + b2 (in place)
    sgemm_kernel<true,true,false><<<dim3(DFF_/128, M_/128), 256>>>(x2, W1, b1, nullptr, hb, M_, DFF_, D_);
    sgemm_kernel<false,true,true><<<gQKV, 256>>>(hb, W2, b2, xo, xo, M_, D_, DFF_);

    // 7. p = x@Wp[:D] + param_x@Wp[D:] + bp
    dim3 gP(P_/128, M_/128);
    sgemm_kernel<false,true,false><<<gP, 256>>>(xo, Wp, bp, nullptr, po, M_, P_, D_);
    sgemm_kernel<false,false,true><<<gP, 256>>>(px, Wp + (size_t)D_ * P_, nullptr, po, po, M_, P_, P_);
}

// round 2
// speedup vs baseline: 1.5730x; 1.5730x over previous
#include <cuda_runtime.h>
#include <cstdint>

// ---------------- problem constants ----------------
#define B_  4
#define S_  2048
#define D_  1024
#define P_  256
#define H_  16
#define DH_ 64
#define DFF_ 512
#define M_  (B_*S_)           // 8192 rows
#define EPS_ 1e-6f

// ---------------- scratch (static device globals; no allocation) ----------------
__device__ float g_xn [M_*D_];
__device__ float g_q  [M_*D_];
__device__ float g_k  [M_*D_];
__device__ float g_v  [M_*D_];
__device__ float g_ctx[M_*D_];
__device__ float g_x2 [M_*D_];
__device__ float g_h  [M_*DFF_];

// ---------------- LayerNorm (torch semantics: unbiased std, eps on std) ----------------
__global__ void ln_kernel(const float* __restrict__ in,
                          const float* __restrict__ alpha,
                          const float* __restrict__ beta,
                          float* __restrict__ out) {
    const int row = blockIdx.x;
    const int t = threadIdx.x;            // 256 threads, 4 elems each
    const float* x = in + (size_t)row * D_;
    float v[4];
    float s = 0.f;
    #pragma unroll
    for (int i = 0; i < 4; i++) { v[i] = x[t + 256*i]; s += v[i]; }

    __shared__ float red[8];
    #pragma unroll
    for (int o = 16; o > 0; o >>= 1) s += __shfl_xor_sync(0xffffffffu, s, o);
    if ((t & 31) == 0) red[t >> 5] = s;
    __syncthreads();
    float tot = 0.f;
    #pragma unroll
    for (int i = 0; i < 8; i++) tot += red[i];
    const float mu = tot * (1.0f / D_);

    float ss = 0.f;
    #pragma unroll
    for (int i = 0; i < 4; i++) { float d = v[i] - mu; ss += d * d; }
    __syncthreads();
    #pragma unroll
    for (int o = 16; o > 0; o >>= 1) ss += __shfl_xor_sync(0xffffffffu, ss, o);
    if ((t & 31) == 0) red[t >> 5] = ss;
    __syncthreads();
    float sst = 0.f;
    #pragma unroll
    for (int i = 0; i < 8; i++) sst += red[i];

    const float stdv = sqrtf(fmaxf(sst, 0.f) * (1.0f / (D_ - 1)));
    const float inv = 1.0f / (stdv + EPS_);
    float* o = out + (size_t)row * D_;
    #pragma unroll
    for (int i = 0; i < 4; i++) {
        int c = t + 256*i;
        o[c] = alpha[c] * (v[i] - mu) * inv + beta[c];
    }
}

// ---------------- tf32 helpers ----------------
__device__ __forceinline__ float to_tf32(float x) {
    uint32_t u;
    asm("cvt.rna.tf32.f32 %0, %1;" : "=r"(u) : "f"(x));
    return __uint_as_float(u);
}

__device__ __forceinline__ void mma_tf32(float c[4], const uint32_t a[4], const uint32_t b[2]) {
    asm volatile(
        "mma.sync.aligned.m16n8k8.row.col.f32.tf32.tf32.f32 "
        "{%0,%1,%2,%3}, {%4,%5,%6,%7}, {%8,%9}, {%0,%1,%2,%3};\n"
        : "+f"(c[0]), "+f"(c[1]), "+f"(c[2]), "+f"(c[3])
        : "r"(a[0]), "r"(a[1]), "r"(a[2]), "r"(a[3]), "r"(b[0]), "r"(b[1]));
}

// ---------------- TF32 tensor-core GEMM: 128x128x32 tiles, 8 warps, 64x32 warp tile ----------------
// C[m,n] = (res? res:0) + A@B + (bias? bias:0), opt ReLU. Requires M%128==0, N%128==0, K%32==0.
#define SA 36                 // A smem row stride (words): 32 + 4 pad
#define SB 136                // B smem row stride (words): 128 + 8 pad
#define ABUF (128*SA)         // 4608 words per A buffer
#define BBUF (32*SB)          // 4352 words per B buffer
#define GEMM_SMEM ((2*ABUF + 2*BBUF) * 4)   // 71680 bytes

template<bool RELU, bool HASBIAS, bool HASRES>
__global__ void mma_gemm_kernel(const float* __restrict__ A, const float* __restrict__ Bm,
                                const float* __restrict__ bias, const float* __restrict__ res,
                                float* __restrict__ C, int M, int N, int K) {
    extern __shared__ float sm[];
    float* As = sm;              // [2][128][SA]
    float* Bs = sm + 2*ABUF;     // [2][32][SB]

    const int t = threadIdx.x;
    const int w = t >> 5, lane = t & 31;
    const int wm = w >> 2, wn = w & 3;       // warp grid 2 (m) x 4 (n)
    const int g = lane >> 2, tg = lane & 3;  // groupID, threadID_in_group
    const int bx = blockIdx.x, by = blockIdx.y;

    const float* Ab = A  + (size_t)by * 128 * K;
    const float* Bb = Bm + (size_t)bx * 128;

    // global-load indices (float4 granularity)
    const int ar = t >> 3, ac = (t & 7) * 4;    // A: rows ar+32i, col ac
    const int br = t >> 5, bc = (t & 31) * 4;   // B: rows br+8i,  col bc

    float4 ra[4], rb[4];

    const int KT = K >> 5;   // K / 32

    // prologue: load tile 0
    #pragma unroll
    for (int i = 0; i < 4; i++)
        ra[i] = *(const float4*)(Ab + (size_t)(ar + 32*i) * K + ac);
    #pragma unroll
    for (int i = 0; i < 4; i++)
        rb[i] = *(const float4*)(Bb + (size_t)(br + 8*i) * N + bc);

    float acc[4][4][4];
    #pragma unroll
    for (int mi = 0; mi < 4; mi++)
        #pragma unroll
        for (int ni = 0; ni < 4; ni++)
            #pragma unroll
            for (int r = 0; r < 4; r++) acc[mi][ni][r] = 0.f;

    // store tile 0 -> buffer 0 (with tf32 rounding)
    {
        float* a = As;
        float* b = Bs;
        #pragma unroll
        for (int i = 0; i < 4; i++) {
            float4 v = ra[i];
            v.x = to_tf32(v.x); v.y = to_tf32(v.y); v.z = to_tf32(v.z); v.w = to_tf32(v.w);
            *(float4*)(a + (ar + 32*i)*SA + ac) = v;
        }
        #pragma unroll
        for (int i = 0; i < 4; i++) {
            float4 v = rb[i];
            v.x = to_tf32(v.x); v.y = to_tf32(v.y); v.z = to_tf32(v.z); v.w = to_tf32(v.w);
            *(float4*)(b + (br + 8*i)*SB + bc) = v;
        }
    }
    __syncthreads();

    for (int kt = 0; kt < KT; kt++) {
        const int cur = kt & 1;
        // prefetch next tile into registers
        if (kt + 1 < KT) {
            const int ko = (kt + 1) * 32;
            #pragma unroll
            for (int i = 0; i < 4; i++)
                ra[i] = *(const float4*)(Ab + (size_t)(ar + 32*i) * K + ko + ac);
            #pragma unroll
            for (int i = 0; i < 4; i++)
                rb[i] = *(const float4*)(Bb + (size_t)(ko + br + 8*i) * N + bc);
        }

        // compute on buffer cur
        const uint32_t* Au = (const uint32_t*)(As + cur*ABUF);
        const uint32_t* Bu = (const uint32_t*)(Bs + cur*BBUF);
        #pragma unroll
        for (int kk = 0; kk < 4; kk++) {
            uint32_t af[4][4];
            #pragma unroll
            for (int mi = 0; mi < 4; mi++) {
                const int base = (wm*64 + mi*16 + g)*SA + kk*8 + tg;
                af[mi][0] = Au[base];
                af[mi][1] = Au[base + 8*SA];
                af[mi][2] = Au[base + 4];
                af[mi][3] = Au[base + 8*SA + 4];
            }
            uint32_t bf[4][2];
            #pragma unroll
            for (int ni = 0; ni < 4; ni++) {
                const int base = (kk*8 + tg)*SB + wn*32 + ni*8 + g;
                bf[ni][0] = Bu[base];
                bf[ni][1] = Bu[base + 4*SB];
            }
            #pragma unroll
            for (int mi = 0; mi < 4; mi++)
                #pragma unroll
                for (int ni = 0; ni < 4; ni++)
                    mma_tf32(acc[mi][ni], af[mi], bf[ni]);
        }

        if (kt + 1 < KT) {
            __syncthreads();   // all warps done reading buffer 1-cur (last read in iter kt-1) & done with cur compute
            float* a = As + (1 - cur)*ABUF;
            float* b = Bs + (1 - cur)*BBUF;
            #pragma unroll
            for (int i = 0; i < 4; i++) {
                float4 v = ra[i];
                v.x = to_tf32(v.x); v.y = to_tf32(v.y); v.z = to_tf32(v.z); v.w = to_tf32(v.w);
                *(float4*)(a + (ar + 32*i)*SA + ac) = v;
            }
            #pragma unroll
            for (int i = 0; i < 4; i++) {
                float4 v = rb[i];
                v.x = to_tf32(v.x); v.y = to_tf32(v.y); v.z = to_tf32(v.z); v.w = to_tf32(v.w);
                *(float4*)(b + (br + 8*i)*SB + bc) = v;
            }
            __syncthreads();
        }
    }

    // epilogue: c0,c1 at (row0, col..col+1), c2,c3 at (row0+8, col..col+1)
    #pragma unroll
    for (int mi = 0; mi < 4; mi++) {
        #pragma unroll
        for (int ni = 0; ni < 4; ni++) {
            const size_t row0 = (size_t)by*128 + wm*64 + mi*16 + g;
            const size_t row1 = row0 + 8;
            const int col = bx*128 + wn*32 + ni*8 + 2*tg;
            float v0 = acc[mi][ni][0], v1 = acc[mi][ni][1];
            float v2 = acc[mi][ni][2], v3 = acc[mi][ni][3];
            if (HASBIAS) {
                const float bb0 = bias[col], bb1 = bias[col+1];
                v0 += bb0; v1 += bb1; v2 += bb0; v3 += bb1;
            }
            if (HASRES) {
                v0 += res[row0*N + col]; v1 += res[row0*N + col + 1];
                v2 += res[row1*N + col]; v3 += res[row1*N + col + 1];
            }
            if (RELU) {
                v0 = fmaxf(v0, 0.f); v1 = fmaxf(v1, 0.f);
                v2 = fmaxf(v2, 0.f); v3 = fmaxf(v3, 0.f);
            }
            *(float2*)&C[row0*N + col] = make_float2(v0, v1);
            *(float2*)&C[row1*N + col] = make_float2(v2, v3);
        }
    }
}

// ---------------- fused attention (flash-style, fp32) ----------------
#define LDP 65
__global__ void attn_kernel(const float* __restrict__ Q, const float* __restrict__ K,
                            const float* __restrict__ V, float* __restrict__ O) {
    extern __shared__ float smf[];
    float* Qs = smf;                // 64*65
    float* Ks = Qs + 64*LDP;
    float* Vs = Ks + 64*LDP;
    float* Ps = Vs + 64*LDP;

    const int qt = blockIdx.x, h = blockIdx.y, b = blockIdx.z;
    const int t = threadIdx.x;
    const int cg = t & 15, rg = t >> 4;
    const int r0 = rg * 4, c0 = cg * 4;

    for (int e = t; e < 64*64; e += 256) {
        int row = e >> 6, d = e & 63;
        Qs[row*LDP + d] = Q[((size_t)(b*S_ + qt*64 + row)) * D_ + h*DH_ + d];
    }
    __syncthreads();

    float m[4], l[4], o[4][4];
    #pragma unroll
    for (int i = 0; i < 4; i++) {
        m[i] = -1e30f; l[i] = 0.f;
        #pragma unroll
        for (int j = 0; j < 4; j++) o[i][j] = 0.f;
    }

    for (int kt = 0; kt < S_/64; kt++) {
        for (int e = t; e < 64*64; e += 256) {
            int row = e >> 6, d = e & 63;
            size_t gidx = ((size_t)(b*S_ + kt*64 + row)) * D_ + h*DH_ + d;
            Ks[row*LDP + d] = K[gidx];
            Vs[row*LDP + d] = V[gidx];
        }
        __syncthreads();

        float acc[4][4];
        #pragma unroll
        for (int i = 0; i < 4; i++)
            #pragma unroll
            for (int j = 0; j < 4; j++) acc[i][j] = 0.f;
        #pragma unroll 8
        for (int kk = 0; kk < 64; kk++) {
            float qv[4], kv[4];
            #pragma unroll
            for (int i = 0; i < 4; i++) qv[i] = Qs[(r0+i)*LDP + kk];
            #pragma unroll
            for (int j = 0; j < 4; j++) kv[j] = Ks[(c0+j)*LDP + kk];
            #pragma unroll
            for (int i = 0; i < 4; i++)
                #pragma unroll
                for (int j = 0; j < 4; j++) acc[i][j] += qv[i] * kv[j];
        }

        #pragma unroll
        for (int i = 0; i < 4; i++) {
            float tm = acc[i][0];
            #pragma unroll
            for (int j = 1; j < 4; j++) tm = fmaxf(tm, acc[i][j]);
            tm *= 0.125f;
            #pragma unroll
            for (int off = 1; off < 16; off <<= 1)
                tm = fmaxf(tm, __shfl_xor_sync(0xffffffffu, tm, off));
            const float mn = fmaxf(m[i], tm);
            const float corr = expf(m[i] - mn);
            float ts = 0.f;
            #pragma unroll
            for (int j = 0; j < 4; j++) {
                acc[i][j] = expf(acc[i][j] * 0.125f - mn);
                ts += acc[i][j];
            }
            #pragma unroll
            for (int off = 1; off < 16; off <<= 1)
                ts += __shfl_xor_sync(0xffffffffu, ts, off);
            l[i] = l[i] * corr + ts;
            m[i] = mn;
            #pragma unroll
            for (int j = 0; j < 4; j++) o[i][j] *= corr;
            #pragma unroll
            for (int j = 0; j < 4; j++) Ps[(r0+i)*LDP + c0 + j] = acc[i][j];
        }
        __syncthreads();

        #pragma unroll 8
        for (int k = 0; k < 64; k++) {
            float pv[4], vv[4];
            #pragma unroll
            for (int i = 0; i < 4; i++) pv[i] = Ps[(r0+i)*LDP + k];
            #pragma unroll
            for (int j = 0; j < 4; j++) vv[j] = Vs[k*LDP + c0 + j];
            #pragma unroll
            for (int i = 0; i < 4; i++)
                #pragma unroll
                for (int j = 0; j < 4; j++) o[i][j] += pv[i] * vv[j];
        }
        __syncthreads();
    }

    #pragma unroll
    for (int i = 0; i < 4; i++) {
        const float invl = 1.0f / l[i];
        float4 wv;
        wv.x = o[i][0]*invl; wv.y = o[i][1]*invl; wv.z = o[i][2]*invl; wv.w = o[i][3]*invl;
        *(float4*)&O[((size_t)(b*S_ + qt*64 + r0 + i)) * D_ + h*DH_ + c0] = wv;
    }
}

// ---------------- host launcher ----------------
extern "C" void kernel_launch(void* const* d_in, const int* in_sizes, int n_in,
                              void* d_out, int out_size) {
    const float* fx  = (const float*)d_in[0];
    const float* px  = (const float*)d_in[1];
    const float* Wq  = (const float*)d_in[2];
    const float* bq  = (const float*)d_in[3];
    const float* Wk  = (const float*)d_in[4];
    const float* bk  = (const float*)d_in[5];
    const float* Wv  = (const float*)d_in[6];
    const float* bv  = (const float*)d_in[7];
    const float* Wo  = (const float*)d_in[8];
    const float* bo  = (const float*)d_in[9];
    const float* a1  = (const float*)d_in[10];
    const float* be1 = (const float*)d_in[11];
    const float* a2  = (const float*)d_in[12];
    const float* be2 = (const float*)d_in[13];
    const float* W1  = (const float*)d_in[14];
    const float* b1  = (const float*)d_in[15];
    const float* W2  = (const float*)d_in[16];
    const float* b2  = (const float*)d_in[17];
    const float* Wp  = (const float*)d_in[18];
    const float* bp  = (const float*)d_in[19];

    float* xo = (float*)d_out;                    // x: M_ x D_
    float* po = xo + (size_t)M_ * D_;             // p: M_ x P_

    float *xn, *q, *k, *v, *ctx, *x2, *hb;
    cudaGetSymbolAddress((void**)&xn,  g_xn);
    cudaGetSymbolAddress((void**)&q,   g_q);
    cudaGetSymbolAddress((void**)&k,   g_k);
    cudaGetSymbolAddress((void**)&v,   g_v);
    cudaGetSymbolAddress((void**)&ctx, g_ctx);
    cudaGetSymbolAddress((void**)&x2,  g_x2);
    cudaGetSymbolAddress((void**)&hb,  g_h);

    const int smem_attn = 4 * 64 * LDP * sizeof(float);   // 66560 B
    cudaFuncSetAttribute(attn_kernel, cudaFuncAttributeMaxDynamicSharedMemorySize, smem_attn);
    cudaFuncSetAttribute(mma_gemm_kernel<false,true,false>, cudaFuncAttributeMaxDynamicSharedMemorySize, GEMM_SMEM);
    cudaFuncSetAttribute(mma_gemm_kernel<false,true,true>,  cudaFuncAttributeMaxDynamicSharedMemorySize, GEMM_SMEM);
    cudaFuncSetAttribute(mma_gemm_kernel<true,true,false>,  cudaFuncAttributeMaxDynamicSharedMemorySize, GEMM_SMEM);
    cudaFuncSetAttribute(mma_gemm_kernel<false,false,true>, cudaFuncAttributeMaxDynamicSharedMemorySize, GEMM_SMEM);

    // 1. xn = LN1(feature_x)
    ln_kernel<<<M_, 256>>>(fx, a1, be1, xn);

    // 2. Q,K,V
    dim3 gQKV(D_/128, M_/128);
    mma_gemm_kernel<false,true,false><<<gQKV, 256, GEMM_SMEM>>>(xn, Wq, bq, nullptr, q, M_, D_, D_);
    mma_gemm_kernel<false,true,false><<<gQKV, 256, GEMM_SMEM>>>(xn, Wk, bk, nullptr, k, M_, D_, D_);
    mma_gemm_kernel<false,true,false><<<gQKV, 256, GEMM_SMEM>>>(xn, Wv, bv, nullptr, v, M_, D_, D_);

    // 3. attention -> ctx
    attn_kernel<<<dim3(S_/64, H_, B_), 256, smem_attn>>>(q, k, v, ctx);

    // 4. x = xn + ctx@Wo + bo
    mma_gemm_kernel<false,true,true><<<gQKV, 256, GEMM_SMEM>>>(ctx, Wo, bo, xn, xo, M_, D_, D_);

    // 5. x2 = LN2(x)
    ln_kernel<<<M_, 256>>>(xo, a2, be2, x2);

    // 6. h = relu(x2@W1+b1); x = x + h@W2 + b2 (in place)
    mma_gemm_kernel<true,true,false><<<dim3(DFF_/128, M_/128), 256, GEMM_SMEM>>>(x2, W1, b1, nullptr, hb, M_, DFF_, D_);
    mma_gemm_kernel<false,true,true><<<gQKV, 256, GEMM_SMEM>>>(hb, W2, b2, xo, xo, M_, D_, DFF_);

    // 7. p = x@Wp[:D] + param_x@Wp[D:] + bp
    dim3 gP(P_/128, M_/128);
    mma_gemm_kernel<false,true,false><<<gP, 256, GEMM_SMEM>>>(xo, Wp, bp, nullptr, po, M_, P_, D_);
    mma_gemm_kernel<false,false,true><<<gP, 256, GEMM_SMEM>>>(px, Wp + (size_t)D_ * P_, nullptr, po, po, M_, P_, P_);
}

// round 3
// speedup vs baseline: 3.2075x; 2.0391x over previous
#include <cuda_runtime.h>
#include <cstdint>

// ---------------- problem constants ----------------
#define B_  4
#define S_  2048
#define D_  1024
#define P_  256
#define H_  16
#define DH_ 64
#define DFF_ 512
#define M_  (B_*S_)           // 8192 rows
#define EPS_ 1e-6f

// ---------------- scratch (static device globals; no allocation) ----------------
__device__ float g_xn [M_*D_];
__device__ float g_q  [M_*D_];
__device__ float g_k  [M_*D_];
__device__ float g_v  [M_*D_];
__device__ float g_ctx[M_*D_];
__device__ float g_x2 [M_*D_];
__device__ float g_h  [M_*DFF_];

// ---------------- LayerNorm (torch semantics: unbiased std, eps on std) ----------------
__global__ void ln_kernel(const float* __restrict__ in,
                          const float* __restrict__ alpha,
                          const float* __restrict__ beta,
                          float* __restrict__ out) {
    const int row = blockIdx.x;
    const int t = threadIdx.x;            // 256 threads, 4 elems each
    const float* x = in + (size_t)row * D_;
    float v[4];
    float s = 0.f;
    #pragma unroll
    for (int i = 0; i < 4; i++) { v[i] = x[t + 256*i]; s += v[i]; }

    __shared__ float red[8];
    #pragma unroll
    for (int o = 16; o > 0; o >>= 1) s += __shfl_xor_sync(0xffffffffu, s, o);
    if ((t & 31) == 0) red[t >> 5] = s;
    __syncthreads();
    float tot = 0.f;
    #pragma unroll
    for (int i = 0; i < 8; i++) tot += red[i];
    const float mu = tot * (1.0f / D_);

    float ss = 0.f;
    #pragma unroll
    for (int i = 0; i < 4; i++) { float d = v[i] - mu; ss += d * d; }
    __syncthreads();
    #pragma unroll
    for (int o = 16; o > 0; o >>= 1) ss += __shfl_xor_sync(0xffffffffu, ss, o);
    if ((t & 31) == 0) red[t >> 5] = ss;
    __syncthreads();
    float sst = 0.f;
    #pragma unroll
    for (int i = 0; i < 8; i++) sst += red[i];

    const float stdv = sqrtf(fmaxf(sst, 0.f) * (1.0f / (D_ - 1)));
    const float inv = 1.0f / (stdv + EPS_);
    float* o = out + (size_t)row * D_;
    #pragma unroll
    for (int i = 0; i < 4; i++) {
        int c = t + 256*i;
        o[c] = alpha[c] * (v[i] - mu) * inv + beta[c];
    }
}

// ---------------- tf32 helpers ----------------
__device__ __forceinline__ float to_tf32(float x) {
    uint32_t u;
    asm("cvt.rna.tf32.f32 %0, %1;" : "=r"(u) : "f"(x));
    return __uint_as_float(u);
}

__device__ __forceinline__ void mma_tf32(float c[4], const uint32_t a[4], const uint32_t b[2]) {
    asm volatile(
        "mma.sync.aligned.m16n8k8.row.col.f32.tf32.tf32.f32 "
        "{%0,%1,%2,%3}, {%4,%5,%6,%7}, {%8,%9}, {%0,%1,%2,%3};\n"
        : "+f"(c[0]), "+f"(c[1]), "+f"(c[2]), "+f"(c[3])
        : "r"(a[0]), "r"(a[1]), "r"(a[2]), "r"(a[3]), "r"(b[0]), "r"(b[1]));
}

// ---------------- TF32 tensor-core GEMM: 128x128x32 tiles, 8 warps, 64x32 warp tile ----------------
#define SA 36
#define SB 136
#define ABUF (128*SA)
#define BBUF (32*SB)
#define GEMM_SMEM ((2*ABUF + 2*BBUF) * 4)   // 71680 bytes

template<bool RELU, bool HASBIAS, bool HASRES>
__global__ void mma_gemm_kernel(const float* __restrict__ A, const float* __restrict__ Bm,
                                const float* __restrict__ bias, const float* __restrict__ res,
                                float* __restrict__ C, int M, int N, int K) {
    extern __shared__ float sm[];
    float* As = sm;              // [2][128][SA]
    float* Bs = sm + 2*ABUF;     // [2][32][SB]

    const int t = threadIdx.x;
    const int w = t >> 5, lane = t & 31;
    const int wm = w >> 2, wn = w & 3;
    const int g = lane >> 2, tg = lane & 3;
    const int bx = blockIdx.x, by = blockIdx.y;

    const float* Ab = A  + (size_t)by * 128 * K;
    const float* Bb = Bm + (size_t)bx * 128;

    const int ar = t >> 3, ac = (t & 7) * 4;
    const int br = t >> 5, bc = (t & 31) * 4;

    float4 ra[4], rb[4];
    const int KT = K >> 5;

    #pragma unroll
    for (int i = 0; i < 4; i++)
        ra[i] = *(const float4*)(Ab + (size_t)(ar + 32*i) * K + ac);
    #pragma unroll
    for (int i = 0; i < 4; i++)
        rb[i] = *(const float4*)(Bb + (size_t)(br + 8*i) * N + bc);

    float acc[4][4][4];
    #pragma unroll
    for (int mi = 0; mi < 4; mi++)
        #pragma unroll
        for (int ni = 0; ni < 4; ni++)
            #pragma unroll
            for (int r = 0; r < 4; r++) acc[mi][ni][r] = 0.f;

    {
        float* a = As;
        float* b = Bs;
        #pragma unroll
        for (int i = 0; i < 4; i++) {
            float4 v = ra[i];
            v.x = to_tf32(v.x); v.y = to_tf32(v.y); v.z = to_tf32(v.z); v.w = to_tf32(v.w);
            *(float4*)(a + (ar + 32*i)*SA + ac) = v;
        }
        #pragma unroll
        for (int i = 0; i < 4; i++) {
            float4 v = rb[i];
            v.x = to_tf32(v.x); v.y = to_tf32(v.y); v.z = to_tf32(v.z); v.w = to_tf32(v.w);
            *(float4*)(b + (br + 8*i)*SB + bc) = v;
        }
    }
    __syncthreads();

    for (int kt = 0; kt < KT; kt++) {
        const int cur = kt & 1;
        if (kt + 1 < KT) {
            const int ko = (kt + 1) * 32;
            #pragma unroll
            for (int i = 0; i < 4; i++)
                ra[i] = *(const float4*)(Ab + (size_t)(ar + 32*i) * K + ko + ac);
            #pragma unroll
            for (int i = 0; i < 4; i++)
                rb[i] = *(const float4*)(Bb + (size_t)(ko + br + 8*i) * N + bc);
        }

        const uint32_t* Au = (const uint32_t*)(As + cur*ABUF);
        const uint32_t* Bu = (const uint32_t*)(Bs + cur*BBUF);
        #pragma unroll
        for (int kk = 0; kk < 4; kk++) {
            uint32_t af[4][4];
            #pragma unroll
            for (int mi = 0; mi < 4; mi++) {
                const int base = (wm*64 + mi*16 + g)*SA + kk*8 + tg;
                af[mi][0] = Au[base];
                af[mi][1] = Au[base + 8*SA];
                af[mi][2] = Au[base + 4];
                af[mi][3] = Au[base + 8*SA + 4];
            }
            uint32_t bf[4][2];
            #pragma unroll
            for (int ni = 0; ni < 4; ni++) {
                const int base = (kk*8 + tg)*SB + wn*32 + ni*8 + g;
                bf[ni][0] = Bu[base];
                bf[ni][1] = Bu[base + 4*SB];
            }
            #pragma unroll
            for (int mi = 0; mi < 4; mi++)
                #pragma unroll
                for (int ni = 0; ni < 4; ni++)
                    mma_tf32(acc[mi][ni], af[mi], bf[ni]);
        }

        if (kt + 1 < KT) {
            __syncthreads();
            float* a = As + (1 - cur)*ABUF;
            float* b = Bs + (1 - cur)*BBUF;
            #pragma unroll
            for (int i = 0; i < 4; i++) {
                float4 v = ra[i];
                v.x = to_tf32(v.x); v.y = to_tf32(v.y); v.z = to_tf32(v.z); v.w = to_tf32(v.w);
                *(float4*)(a + (ar + 32*i)*SA + ac) = v;
            }
            #pragma unroll
            for (int i = 0; i < 4; i++) {
                float4 v = rb[i];
                v.x = to_tf32(v.x); v.y = to_tf32(v.y); v.z = to_tf32(v.z); v.w = to_tf32(v.w);
                *(float4*)(b + (br + 8*i)*SB + bc) = v;
            }
            __syncthreads();
        }
    }

    #pragma unroll
    for (int mi = 0; mi < 4; mi++) {
        #pragma unroll
        for (int ni = 0; ni < 4; ni++) {
            const size_t row0 = (size_t)by*128 + wm*64 + mi*16 + g;
            const size_t row1 = row0 + 8;
            const int col = bx*128 + wn*32 + ni*8 + 2*tg;
            float v0 = acc[mi][ni][0], v1 = acc[mi][ni][1];
            float v2 = acc[mi][ni][2], v3 = acc[mi][ni][3];
            if (HASBIAS) {
                const float bb0 = bias[col], bb1 = bias[col+1];
                v0 += bb0; v1 += bb1; v2 += bb0; v3 += bb1;
            }
            if (HASRES) {
                v0 += res[row0*N + col]; v1 += res[row0*N + col + 1];
                v2 += res[row1*N + col]; v3 += res[row1*N + col + 1];
            }
            if (RELU) {
                v0 = fmaxf(v0, 0.f); v1 = fmaxf(v1, 0.f);
                v2 = fmaxf(v2, 0.f); v3 = fmaxf(v3, 0.f);
            }
            *(float2*)&C[row0*N + col] = make_float2(v0, v1);
            *(float2*)&C[row1*N + col] = make_float2(v2, v3);
        }
    }
}

// ---------------- tensor-core flash attention (tf32 mma, fp32 softmax) ----------------
// 128 threads (4 warps), 64 queries per CTA (16 rows/warp), 64-key tiles, dh=64.
#define KS 68   // Ks/Ps stride (words): bank = 4g+tg -> conflict-free
#define VS 72   // Vs stride (words):    bank = 8tg+g -> conflict-free
#define ATTN_SMEM ((64*KS + 64*VS + 64*KS) * 4)   // 53248 B

__global__ __launch_bounds__(128, 3)
void attn_kernel(const float* __restrict__ Q, const float* __restrict__ K,
                 const float* __restrict__ V, float* __restrict__ O) {
    extern __shared__ float smf[];
    float* Ks = smf;                 // [64][KS]
    float* Vs = Ks + 64*KS;          // [64][VS]
    float* Ps = Vs + 64*VS;          // [64][KS]  (also Q staging)

    const int qt = blockIdx.x, h = blockIdx.y, b = blockIdx.z;
    const int t = threadIdx.x;
    const int wq = t >> 5, lane = t & 31;
    const int g = lane >> 2, tg = lane & 3;

    const size_t headoff = (size_t)h * DH_;

    // ---- stage Q tile into Ps, convert to tf32 ----
    for (int i = 0; i < 8; i++) {
        const int idx = t + 128*i;          // 1024 float4s
        const int row = idx >> 4, c4 = (idx & 15) * 4;
        float4 v = *(const float4*)(Q + ((size_t)(b*S_ + qt*64 + row)) * D_ + headoff + c4);
        v.x = to_tf32(v.x); v.y = to_tf32(v.y); v.z = to_tf32(v.z); v.w = to_tf32(v.w);
        *(float4*)(Ps + row*KS + c4) = v;
    }
    __syncthreads();

    // ---- preload Q fragments (warp-private rows wq*16..wq*16+15) ----
    uint32_t aQ[8][4];
    {
        const uint32_t* Pu = (const uint32_t*)Ps;
        #pragma unroll
        for (int kk = 0; kk < 8; kk++) {
            const int base = (wq*16 + g)*KS + kk*8 + tg;
            aQ[kk][0] = Pu[base];
            aQ[kk][1] = Pu[base + 8*KS];
            aQ[kk][2] = Pu[base + 4];
            aQ[kk][3] = Pu[base + 8*KS + 4];
        }
    }

    float m[2], l[2], o[8][4];
    m[0] = m[1] = -1e30f; l[0] = l[1] = 0.f;
    #pragma unroll
    for (int ni = 0; ni < 8; ni++)
        #pragma unroll
        for (int r = 0; r < 4; r++) o[ni][r] = 0.f;

    for (int kt = 0; kt < S_/64; kt++) {
        __syncthreads();   // everyone done reading Ks/Vs (and Q staging on first iter)
        // ---- load K,V tile (tf32) ----
        for (int i = 0; i < 8; i++) {
            const int idx = t + 128*i;
            const int row = idx >> 4, c4 = (idx & 15) * 4;
            const size_t gp = ((size_t)(b*S_ + kt*64 + row)) * D_ + headoff + c4;
            float4 kv = *(const float4*)(K + gp);
            kv.x = to_tf32(kv.x); kv.y = to_tf32(kv.y); kv.z = to_tf32(kv.z); kv.w = to_tf32(kv.w);
            *(float4*)(Ks + row*KS + c4) = kv;
            float4 vv = *(const float4*)(V + gp);
            vv.x = to_tf32(vv.x); vv.y = to_tf32(vv.y); vv.z = to_tf32(vv.z); vv.w = to_tf32(vv.w);
            *(float4*)(Vs + row*VS + c4) = vv;
        }
        __syncthreads();

        // ---- S = Q K^T ----
        float acc[8][4];
        #pragma unroll
        for (int ni = 0; ni < 8; ni++)
            #pragma unroll
            for (int r = 0; r < 4; r++) acc[ni][r] = 0.f;

        const uint32_t* Ku = (const uint32_t*)Ks;
        #pragma unroll
        for (int kk = 0; kk < 8; kk++) {
            #pragma unroll
            for (int ni = 0; ni < 8; ni++) {
                uint32_t bf[2];
                const int base = (ni*8 + g)*KS + kk*8 + tg;
                bf[0] = Ku[base];
                bf[1] = Ku[base + 4];
                mma_tf32(acc[ni], aQ[kk], bf);
            }
        }

        // ---- online softmax (rows g and g+8 of this warp's 16-row slice) ----
        #pragma unroll
        for (int ni = 0; ni < 8; ni++)
            #pragma unroll
            for (int r = 0; r < 4; r++) acc[ni][r] *= 0.125f;

        float tm0 = -1e30f, tm1 = -1e30f;
        #pragma unroll
        for (int ni = 0; ni < 8; ni++) {
            tm0 = fmaxf(tm0, fmaxf(acc[ni][0], acc[ni][1]));
            tm1 = fmaxf(tm1, fmaxf(acc[ni][2], acc[ni][3]));
        }
        #pragma unroll
        for (int off = 1; off < 4; off <<= 1) {
            tm0 = fmaxf(tm0, __shfl_xor_sync(0xffffffffu, tm0, off));
            tm1 = fmaxf(tm1, __shfl_xor_sync(0xffffffffu, tm1, off));
        }
        const float mn0 = fmaxf(m[0], tm0);
        const float mn1 = fmaxf(m[1], tm1);
        const float corr0 = __expf(m[0] - mn0);
        const float corr1 = __expf(m[1] - mn1);
        float ts0 = 0.f, ts1 = 0.f;
        #pragma unroll
        for (int ni = 0; ni < 8; ni++) {
            acc[ni][0] = __expf(acc[ni][0] - mn0);
            acc[ni][1] = __expf(acc[ni][1] - mn0);
            acc[ni][2] = __expf(acc[ni][2] - mn1);
            acc[ni][3] = __expf(acc[ni][3] - mn1);
            ts0 += acc[ni][0] + acc[ni][1];
            ts1 += acc[ni][2] + acc[ni][3];
        }
        #pragma unroll
        for (int off = 1; off < 4; off <<= 1) {
            ts0 += __shfl_xor_sync(0xffffffffu, ts0, off);
            ts1 += __shfl_xor_sync(0xffffffffu, ts1, off);
        }
        l[0] = l[0]*corr0 + ts0;  m[0] = mn0;
        l[1] = l[1]*corr1 + ts1;  m[1] = mn1;
        #pragma unroll
        for (int ni = 0; ni < 8; ni++) {
            o[ni][0] *= corr0; o[ni][1] *= corr0;
            o[ni][2] *= corr1; o[ni][3] *= corr1;
        }

        // ---- store P (tf32) to warp-private smem slice ----
        #pragma unroll
        for (int ni = 0; ni < 8; ni++) {
            const int col = ni*8 + 2*tg;
            *(float2*)(Ps + (wq*16 + g    )*KS + col) = make_float2(to_tf32(acc[ni][0]), to_tf32(acc[ni][1]));
            *(float2*)(Ps + (wq*16 + g + 8)*KS + col) = make_float2(to_tf32(acc[ni][2]), to_tf32(acc[ni][3]));
        }
        __syncwarp();

        // ---- O += P V ----
        const uint32_t* Pu = (const uint32_t*)Ps;
        const uint32_t* Vu = (const uint32_t*)Vs;
        #pragma unroll
        for (int kk = 0; kk < 8; kk++) {
            uint32_t aP[4];
            const int pbase = (wq*16 + g)*KS + kk*8 + tg;
            aP[0] = Pu[pbase];
            aP[1] = Pu[pbase + 8*KS];
            aP[2] = Pu[pbase + 4];
            aP[3] = Pu[pbase + 8*KS + 4];
            #pragma unroll
            for (int ni = 0; ni < 8; ni++) {
                uint32_t bf[2];
                const int vbase = (kk*8 + tg)*VS + ni*8 + g;
                bf[0] = Vu[vbase];
                bf[1] = Vu[vbase + 4*VS];
                mma_tf32(o[ni], aP, bf);
            }
        }
    }

    // ---- epilogue: O /= l ----
    const float inv0 = 1.0f / l[0];
    const float inv1 = 1.0f / l[1];
    const size_t row0 = (size_t)(b*S_ + qt*64 + wq*16 + g);
    const size_t row1 = row0 + 8;
    #pragma unroll
    for (int ni = 0; ni < 8; ni++) {
        const int col = ni*8 + 2*tg;
        *(float2*)&O[row0*D_ + headoff + col] = make_float2(o[ni][0]*inv0, o[ni][1]*inv0);
        *(float2*)&O[row1*D_ + headoff + col] = make_float2(o[ni][2]*inv1, o[ni][3]*inv1);
    }
}

// ---------------- host launcher ----------------
extern "C" void kernel_launch(void* const* d_in, const int* in_sizes, int n_in,
                              void* d_out, int out_size) {
    const float* fx  = (const float*)d_in[0];
    const float* px  = (const float*)d_in[1];
    const float* Wq  = (const float*)d_in[2];
    const float* bq  = (const float*)d_in[3];
    const float* Wk  = (const float*)d_in[4];
    const float* bk  = (const float*)d_in[5];
    const float* Wv  = (const float*)d_in[6];
    const float* bv  = (const float*)d_in[7];
    const float* Wo  = (const float*)d_in[8];
    const float* bo  = (const float*)d_in[9];
    const float* a1  = (const float*)d_in[10];
    const float* be1 = (const float*)d_in[11];
    const float* a2  = (const float*)d_in[12];
    const float* be2 = (const float*)d_in[13];
    const float* W1  = (const float*)d_in[14];
    const float* b1  = (const float*)d_in[15];
    const float* W2  = (const float*)d_in[16];
    const float* b2  = (const float*)d_in[17];
    const float* Wp  = (const float*)d_in[18];
    const float* bp  = (const float*)d_in[19];

    float* xo = (float*)d_out;                    // x: M_ x D_
    float* po = xo + (size_t)M_ * D_;             // p: M_ x P_

    float *xn, *q, *k, *v, *ctx, *x2, *hb;
    cudaGetSymbolAddress((void**)&xn,  g_xn);
    cudaGetSymbolAddress((void**)&q,   g_q);
    cudaGetSymbolAddress((void**)&k,   g_k);
    cudaGetSymbolAddress((void**)&v,   g_v);
    cudaGetSymbolAddress((void**)&ctx, g_ctx);
    cudaGetSymbolAddress((void**)&x2,  g_x2);
    cudaGetSymbolAddress((void**)&hb,  g_h);

    cudaFuncSetAttribute(attn_kernel, cudaFuncAttributeMaxDynamicSharedMemorySize, ATTN_SMEM);
    cudaFuncSetAttribute(mma_gemm_kernel<false,true,false>, cudaFuncAttributeMaxDynamicSharedMemorySize, GEMM_SMEM);
    cudaFuncSetAttribute(mma_gemm_kernel<false,true,true>,  cudaFuncAttributeMaxDynamicSharedMemorySize, GEMM_SMEM);
    cudaFuncSetAttribute(mma_gemm_kernel<true,true,false>,  cudaFuncAttributeMaxDynamicSharedMemorySize, GEMM_SMEM);
    cudaFuncSetAttribute(mma_gemm_kernel<false,false,true>, cudaFuncAttributeMaxDynamicSharedMemorySize, GEMM_SMEM);

    // 1. xn = LN1(feature_x)
    ln_kernel<<<M_, 256>>>(fx, a1, be1, xn);

    // 2. Q,K,V
    dim3 gQKV(D_/128, M_/128);
    mma_gemm_kernel<false,true,false><<<gQKV, 256, GEMM_SMEM>>>(xn, Wq, bq, nullptr, q, M_, D_, D_);
    mma_gemm_kernel<false,true,false><<<gQKV, 256, GEMM_SMEM>>>(xn, Wk, bk, nullptr, k, M_, D_, D_);
    mma_gemm_kernel<false,true,false><<<gQKV, 256, GEMM_SMEM>>>(xn, Wv, bv, nullptr, v, M_, D_, D_);

    // 3. attention -> ctx (tensor cores)
    attn_kernel<<<dim3(S_/64, H_, B_), 128, ATTN_SMEM>>>(q, k, v, ctx);

    // 4. x = xn + ctx@Wo + bo
    mma_gemm_kernel<false,true,true><<<gQKV, 256, GEMM_SMEM>>>(ctx, Wo, bo, xn, xo, M_, D_, D_);

    // 5. x2 = LN2(x)
    ln_kernel<<<M_, 256>>>(xo, a2, be2, x2);

    // 6. h = relu(x2@W1+b1); x = x + h@W2 + b2 (in place)
    mma_gemm_kernel<true,true,false><<<dim3(DFF_/128, M_/128), 256, GEMM_SMEM>>>(x2, W1, b1, nullptr, hb, M_, DFF_, D_);
    mma_gemm_kernel<false,true,true><<<gQKV, 256, GEMM_SMEM>>>(hb, W2, b2, xo, xo, M_, D_, DFF_);

    // 7. p = x@Wp[:D] + param_x@Wp[D:] + bp
    dim3 gP(P_/128, M_/128);
    mma_gemm_kernel<false,true,false><<<gP, 256, GEMM_SMEM>>>(xo, Wp, bp, nullptr, po, M_, P_, D_);
    mma_gemm_kernel<false,false,true><<<gP, 256, GEMM_SMEM>>>(px, Wp + (size_t)D_ * P_, nullptr, po, po, M_, P_, P_);
}

// round 5
// speedup vs baseline: 3.3536x; 1.0455x over previous
#include <cuda_runtime.h>
#include <cstdint>

// ---------------- problem constants ----------------
#define B_  4
#define S_  2048
#define D_  1024
#define P_  256
#define H_  16
#define DH_ 64
#define DFF_ 512
#define M_  (B_*S_)           // 8192 rows
#define EPS_ 1e-6f

// ---------------- scratch (static device globals; no allocation) ----------------
__device__ float g_xn [M_*D_];
__device__ float g_xnr[M_*D_];
__device__ float g_q  [M_*D_];
__device__ float g_k  [M_*D_];
__device__ float g_v  [M_*D_];
__device__ float g_ctx[M_*D_];
__device__ float g_x2 [M_*D_];
__device__ float g_h  [M_*DFF_];
__device__ float g_xr [M_*D_];
__device__ float g_wq [D_*D_];
__device__ float g_wk [D_*D_];
__device__ float g_wv [D_*D_];
__device__ float g_wo [D_*D_];
__device__ float g_w1 [D_*DFF_];
__device__ float g_w2 [DFF_*D_];
__device__ float g_wp [(D_+P_)*P_];
__device__ float g_px [M_*P_];

// ---------------- tf32 / ptx helpers ----------------
__device__ __forceinline__ float to_tf32(float x) {
    uint32_t u;
    asm("cvt.rna.tf32.f32 %0, %1;" : "=r"(u) : "f"(x));
    return __uint_as_float(u);
}

__device__ __forceinline__ void mma_tf32(float c[4], const uint32_t a[4], const uint32_t b[2]) {
    asm volatile(
        "mma.sync.aligned.m16n8k8.row.col.f32.tf32.tf32.f32 "
        "{%0,%1,%2,%3}, {%4,%5,%6,%7}, {%8,%9}, {%0,%1,%2,%3};\n"
        : "+f"(c[0]), "+f"(c[1]), "+f"(c[2]), "+f"(c[3])
        : "r"(a[0]), "r"(a[1]), "r"(a[2]), "r"(a[3]), "r"(b[0]), "r"(b[1]));
}

__device__ __forceinline__ uint32_t smem_u32(const void* p) {
    uint32_t a;
    asm("{ .reg .u64 t; cvta.to.shared.u64 t, %1; cvt.u32.u64 %0, t; }" : "=r"(a) : "l"(p));
    return a;
}

__device__ __forceinline__ void cp16(uint32_t dst, const float* src) {
    asm volatile("cp.async.ca.shared.global [%0], [%1], 16;" :: "r"(dst), "l"(src));
}
__device__ __forceinline__ void cp_commit() {
    asm volatile("cp.async.commit_group;" ::: "memory");
}
template<int N_>
__device__ __forceinline__ void cp_wait() {
    asm volatile("cp.async.wait_group %0;" :: "n"(N_) : "memory");
}

// ---------------- rounding prep ----------------
__global__ void round_kernel(const float* __restrict__ in, float* __restrict__ out, int n) {
    int i = (blockIdx.x * 256 + threadIdx.x) * 4;
    if (i < n) {
        float4 v = *(const float4*)(in + i);
        v.x = to_tf32(v.x); v.y = to_tf32(v.y); v.z = to_tf32(v.z); v.w = to_tf32(v.w);
        *(float4*)(out + i) = v;
    }
}

// ---------------- LayerNorm: exact output + tf32-rounded output ----------------
__global__ void ln_kernel(const float* __restrict__ in,
                          const float* __restrict__ alpha,
                          const float* __restrict__ beta,
                          float* __restrict__ out,      // exact (may equal outr)
                          float* __restrict__ outr) {   // tf32-rounded
    const int row = blockIdx.x;
    const int t = threadIdx.x;            // 256 threads, 4 elems each
    const float* x = in + (size_t)row * D_;
    float v[4];
    float s = 0.f;
    #pragma unroll
    for (int i = 0; i < 4; i++) { v[i] = x[t + 256*i]; s += v[i]; }

    __shared__ float red[8];
    #pragma unroll
    for (int o = 16; o > 0; o >>= 1) s += __shfl_xor_sync(0xffffffffu, s, o);
    if ((t & 31) == 0) red[t >> 5] = s;
    __syncthreads();
    float tot = 0.f;
    #pragma unroll
    for (int i = 0; i < 8; i++) tot += red[i];
    const float mu = tot * (1.0f / D_);

    float ss = 0.f;
    #pragma unroll
    for (int i = 0; i < 4; i++) { float d = v[i] - mu; ss += d * d; }
    __syncthreads();
    #pragma unroll
    for (int o = 16; o > 0; o >>= 1) ss += __shfl_xor_sync(0xffffffffu, ss, o);
    if ((t & 31) == 0) red[t >> 5] = ss;
    __syncthreads();
    float sst = 0.f;
    #pragma unroll
    for (int i = 0; i < 8; i++) sst += red[i];

    const float stdv = sqrtf(fmaxf(sst, 0.f) * (1.0f / (D_ - 1)));
    const float inv = 1.0f / (stdv + EPS_);
    float* o  = out  + (size_t)row * D_;
    float* orr = outr + (size_t)row * D_;
    #pragma unroll
    for (int i = 0; i < 4; i++) {
        int c = t + 256*i;
        const float y = alpha[c] * (v[i] - mu) * inv + beta[c];
        orr[c] = to_tf32(y);
        if (out != outr) o[c] = y;
    }
}

// ---------------- TF32 mma GEMM: 128x128x32 tiles, cp.async 3-stage pipeline ----------------
// All A/B inputs MUST be pre-rounded to tf32.
#define SA 36
#define SB 136
#define ABYTES (128*SA*4)       // 18432
#define BBYTES (32*SB*4)        // 17408
#define STG (ABYTES + BBYTES)   // 35840
#define GEMM_SMEM (3*STG)       // 107520

template<bool RELU, bool HASBIAS, bool HASRES>
__global__ __launch_bounds__(256, 2)
void tc_gemm(const float* __restrict__ A, const float* __restrict__ Bm,
             const float* __restrict__ bias, const float* __restrict__ res,
             float* __restrict__ C, float* __restrict__ C2,
             int M, int N, int K) {
    extern __shared__ float sm[];
    const uint32_t sb = smem_u32(sm);
    const int t = threadIdx.x;
    const int w = t >> 5, lane = t & 31;
    const int wm = w >> 2, wn = w & 3;       // warp grid 2 (m) x 4 (n)
    const int g = lane >> 2, tg = lane & 3;
    const int bx = blockIdx.x, by = blockIdx.y;

    const float* Ab = A  + (size_t)by * 128 * K;
    const float* Bb = Bm + (size_t)bx * 128;
    const int KT = K >> 5;

    // cp.async mappings (16B chunks)
    const int arow = t >> 3, acol = (t & 7) * 4;    // A rows arow+32j, 32 floats/row
    const int brow = t >> 5, bcol = (t & 31) * 4;   // B rows brow+8j, 128 floats/row

    // prologue: stages 0 and 1
    #pragma unroll
    for (int s = 0; s < 2; s++) {
        const uint32_t as = sb + s*STG;
        const uint32_t bs = as + ABYTES;
        const float* Ap = Ab + s*32;
        const float* Bp = Bb + (size_t)s*32*N;
        #pragma unroll
        for (int j = 0; j < 4; j++)
            cp16(as + ((arow + 32*j)*SA + acol)*4, Ap + (size_t)(arow + 32*j)*K + acol);
        #pragma unroll
        for (int j = 0; j < 4; j++)
            cp16(bs + ((brow + 8*j)*SB + bcol)*4, Bp + (size_t)(brow + 8*j)*N + bcol);
        cp_commit();
    }

    float acc[4][4][4];
    #pragma unroll
    for (int mi = 0; mi < 4; mi++)
        #pragma unroll
        for (int ni = 0; ni < 4; ni++)
            #pragma unroll
            for (int r = 0; r < 4; r++) acc[mi][ni][r] = 0.f;

    for (int kt = 0; kt < KT; kt++) {
        cp_wait<1>();
        __syncthreads();

        // prefetch stage kt+2
        if (kt + 2 < KT) {
            const int s = (kt + 2) % 3;
            const uint32_t as = sb + s*STG;
            const uint32_t bs = as + ABYTES;
            const float* Ap = Ab + (kt + 2)*32;
            const float* Bp = Bb + (size_t)(kt + 2)*32*N;
            #pragma unroll
            for (int j = 0; j < 4; j++)
                cp16(as + ((arow + 32*j)*SA + acol)*4, Ap + (size_t)(arow + 32*j)*K + acol);
            #pragma unroll
            for (int j = 0; j < 4; j++)
                cp16(bs + ((brow + 8*j)*SB + bcol)*4, Bp + (size_t)(brow + 8*j)*N + bcol);
        }
        cp_commit();

        // compute on stage kt%3
        const int cs = kt % 3;
        const uint32_t* Au = (const uint32_t*)(sm + cs*(STG/4));
        const uint32_t* Bu = (const uint32_t*)(sm + cs*(STG/4) + ABYTES/4);
        #pragma unroll
        for (int kk = 0; kk < 4; kk++) {
            uint32_t af[4][4];
            #pragma unroll
            for (int mi = 0; mi < 4; mi++) {
                const int base = (wm*64 + mi*16 + g)*SA + kk*8 + tg;
                af[mi][0] = Au[base];
                af[mi][1] = Au[base + 8*SA];
                af[mi][2] = Au[base + 4];
                af[mi][3] = Au[base + 8*SA + 4];
            }
            uint32_t bf[4][2];
            #pragma unroll
            for (int ni = 0; ni < 4; ni++) {
                const int base = (kk*8 + tg)*SB + wn*32 + ni*8 + g;
                bf[ni][0] = Bu[base];
                bf[ni][1] = Bu[base + 4*SB];
            }
            #pragma unroll
            for (int mi = 0; mi < 4; mi++)
                #pragma unroll
                for (int ni = 0; ni < 4; ni++)
                    mma_tf32(acc[mi][ni], af[mi], bf[ni]);
        }
    }

    // epilogue
    #pragma unroll
    for (int mi = 0; mi < 4; mi++) {
        #pragma unroll
        for (int ni = 0; ni < 4; ni++) {
            const size_t row0 = (size_t)by*128 + wm*64 + mi*16 + g;
            const size_t row1 = row0 + 8;
            const int col = bx*128 + wn*32 + ni*8 + 2*tg;
            float v0 = acc[mi][ni][0], v1 = acc[mi][ni][1];
            float v2 = acc[mi][ni][2], v3 = acc[mi][ni][3];
            if (HASBIAS) {
                const float bb0 = bias[col], bb1 = bias[col+1];
                v0 += bb0; v1 += bb1; v2 += bb0; v3 += bb1;
            }
            if (HASRES) {
                v0 += res[row0*N + col]; v1 += res[row0*N + col + 1];
                v2 += res[row1*N + col]; v3 += res[row1*N + col + 1];
            }
            if (RELU) {
                v0 = fmaxf(v0, 0.f); v1 = fmaxf(v1, 0.f);
                v2 = fmaxf(v2, 0.f); v3 = fmaxf(v3, 0.f);
            }
            if (C2) {
                *(float2*)&C2[row0*N + col] = make_float2(to_tf32(v0), to_tf32(v1));
                *(float2*)&C2[row1*N + col] = make_float2(to_tf32(v2), to_tf32(v3));
            }
            if (C != C2) {
                *(float2*)&C[row0*N + col] = make_float2(v0, v1);
                *(float2*)&C[row1*N + col] = make_float2(v2, v3);
            }
        }
    }
}

// ---------------- tensor-core flash attention (tf32 mma, fp32 softmax) ----------------
// 128 threads (4 warps), 64 queries per CTA (16 rows/warp), 64-key tiles, dh=64.
#define KS 68   // Ks/Ps stride (words)
#define VS 72   // Vs stride (words)
#define ATTN_SMEM ((64*KS + 64*VS + 64*KS) * 4)   // 53248 B

__global__ __launch_bounds__(128, 3)
void attn_kernel(const float* __restrict__ Q, const float* __restrict__ K,
                 const float* __restrict__ V, float* __restrict__ O) {
    extern __shared__ float smf[];
    float* Ks = smf;                 // [64][KS]
    float* Vs = Ks + 64*KS;          // [64][VS]
    float* Ps = Vs + 64*VS;          // [64][KS]  (also Q staging)

    const int qt = blockIdx.x, h = blockIdx.y, b = blockIdx.z;
    const int t = threadIdx.x;
    const int wq = t >> 5, lane = t & 31;
    const int g = lane >> 2, tg = lane & 3;

    const size_t headoff = (size_t)h * DH_;

    for (int i = 0; i < 8; i++) {
        const int idx = t + 128*i;
        const int row = idx >> 4, c4 = (idx & 15) * 4;
        float4 v = *(const float4*)(Q + ((size_t)(b*S_ + qt*64 + row)) * D_ + headoff + c4);
        v.x = to_tf32(v.x); v.y = to_tf32(v.y); v.z = to_tf32(v.z); v.w = to_tf32(v.w);
        *(float4*)(Ps + row*KS + c4) = v;
    }
    __syncthreads();

    uint32_t aQ[8][4];
    {
        const uint32_t* Pu = (const uint32_t*)Ps;
        #pragma unroll
        for (int kk = 0; kk < 8; kk++) {
            const int base = (wq*16 + g)*KS + kk*8 + tg;
            aQ[kk][0] = Pu[base];
            aQ[kk][1] = Pu[base + 8*KS];
            aQ[kk][2] = Pu[base + 4];
            aQ[kk][3] = Pu[base + 8*KS + 4];
        }
    }

    float m[2], l[2], o[8][4];
    m[0] = m[1] = -1e30f; l[0] = l[1] = 0.f;
    #pragma unroll
    for (int ni = 0; ni < 8; ni++)
        #pragma unroll
        for (int r = 0; r < 4; r++) o[ni][r] = 0.f;

    for (int kt = 0; kt < S_/64; kt++) {
        __syncthreads();
        for (int i = 0; i < 8; i++) {
            const int idx = t + 128*i;
            const int row = idx >> 4, c4 = (idx & 15) * 4;
            const size_t gp = ((size_t)(b*S_ + kt*64 + row)) * D_ + headoff + c4;
            float4 kv = *(const float4*)(K + gp);
            kv.x = to_tf32(kv.x); kv.y = to_tf32(kv.y); kv.z = to_tf32(kv.z); kv.w = to_tf32(kv.w);
            *(float4*)(Ks + row*KS + c4) = kv;
            float4 vv = *(const float4*)(V + gp);
            vv.x = to_tf32(vv.x); vv.y = to_tf32(vv.y); vv.z = to_tf32(vv.z); vv.w = to_tf32(vv.w);
            *(float4*)(Vs + row*VS + c4) = vv;
        }
        __syncthreads();

        float acc[8][4];
        #pragma unroll
        for (int ni = 0; ni < 8; ni++)
            #pragma unroll
            for (int r = 0; r < 4; r++) acc[ni][r] = 0.f;

        const uint32_t* Ku = (const uint32_t*)Ks;
        #pragma unroll
        for (int kk = 0; kk < 8; kk++) {
            #pragma unroll
            for (int ni = 0; ni < 8; ni++) {
                uint32_t bf[2];
                const int base = (ni*8 + g)*KS + kk*8 + tg;
                bf[0] = Ku[base];
                bf[1] = Ku[base + 4];
                mma_tf32(acc[ni], aQ[kk], bf);
            }
        }

        #pragma unroll
        for (int ni = 0; ni < 8; ni++)
            #pragma unroll
            for (int r = 0; r < 4; r++) acc[ni][r] *= 0.125f;

        float tm0 = -1e30f, tm1 = -1e30f;
        #pragma unroll
        for (int ni = 0; ni < 8; ni++) {
            tm0 = fmaxf(tm0, fmaxf(acc[ni][0], acc[ni][1]));
            tm1 = fmaxf(tm1, fmaxf(acc[ni][2], acc[ni][3]));
        }
        #pragma unroll
        for (int off = 1; off < 4; off <<= 1) {
            tm0 = fmaxf(tm0, __shfl_xor_sync(0xffffffffu, tm0, off));
            tm1 = fmaxf(tm1, __shfl_xor_sync(0xffffffffu, tm1, off));
        }
        const float mn0 = fmaxf(m[0], tm0);
        const float mn1 = fmaxf(m[1], tm1);
        const float corr0 = __expf(m[0] - mn0);
        const float corr1 = __expf(m[1] - mn1);
        float ts0 = 0.f, ts1 = 0.f;
        #pragma unroll
        for (int ni = 0; ni < 8; ni++) {
            acc[ni][0] = __expf(acc[ni][0] - mn0);
            acc[ni][1] = __expf(acc[ni][1] - mn0);
            acc[ni][2] = __expf(acc[ni][2] - mn1);
            acc[ni][3] = __expf(acc[ni][3] - mn1);
            ts0 += acc[ni][0] + acc[ni][1];
            ts1 += acc[ni][2] + acc[ni][3];
        }
        #pragma unroll
        for (int off = 1; off < 4; off <<= 1) {
            ts0 += __shfl_xor_sync(0xffffffffu, ts0, off);
            ts1 += __shfl_xor_sync(0xffffffffu, ts1, off);
        }
        l[0] = l[0]*corr0 + ts0;  m[0] = mn0;
        l[1] = l[1]*corr1 + ts1;  m[1] = mn1;
        #pragma unroll
        for (int ni = 0; ni < 8; ni++) {
            o[ni][0] *= corr0; o[ni][1] *= corr0;
            o[ni][2] *= corr1; o[ni][3] *= corr1;
        }

        #pragma unroll
        for (int ni = 0; ni < 8; ni++) {
            const int col = ni*8 + 2*tg;
            *(float2*)(Ps + (wq*16 + g    )*KS + col) = make_float2(to_tf32(acc[ni][0]), to_tf32(acc[ni][1]));
            *(float2*)(Ps + (wq*16 + g + 8)*KS + col) = make_float2(to_tf32(acc[ni][2]), to_tf32(acc[ni][3]));
        }
        __syncwarp();

        const uint32_t* Pu = (const uint32_t*)Ps;
        const uint32_t* Vu = (const uint32_t*)Vs;
        #pragma unroll
        for (int kk = 0; kk < 8; kk++) {
            uint32_t aP[4];
            const int pbase = (wq*16 + g)*KS + kk*8 + tg;
            aP[0] = Pu[pbase];
            aP[1] = Pu[pbase + 8*KS];
            aP[2] = Pu[pbase + 4];
            aP[3] = Pu[pbase + 8*KS + 4];
            #pragma unroll
            for (int ni = 0; ni < 8; ni++) {
                uint32_t bf[2];
                const int vbase = (kk*8 + tg)*VS + ni*8 + g;
                bf[0] = Vu[vbase];
                bf[1] = Vu[vbase + 4*VS];
                mma_tf32(o[ni], aP, bf);
            }
        }
    }

    // epilogue: write ctx rounded to tf32 (it is consumed only as GEMM input)
    const float inv0 = 1.0f / l[0];
    const float inv1 = 1.0f / l[1];
    const size_t row0 = (size_t)(b*S_ + qt*64 + wq*16 + g);
    const size_t row1 = row0 + 8;
    #pragma unroll
    for (int ni = 0; ni < 8; ni++) {
        const int col = ni*8 + 2*tg;
        *(float2*)&O[row0*D_ + headoff + col] = make_float2(to_tf32(o[ni][0]*inv0), to_tf32(o[ni][1]*inv0));
        *(float2*)&O[row1*D_ + headoff + col] = make_float2(to_tf32(o[ni][2]*inv1), to_tf32(o[ni][3]*inv1));
    }
}

// ---------------- host launcher ----------------
extern "C" void kernel_launch(void* const* d_in, const int* in_sizes, int n_in,
                              void* d_out, int out_size) {
    const float* fx  = (const float*)d_in[0];
    const float* px  = (const float*)d_in[1];
    const float* Wq  = (const float*)d_in[2];
    const float* bq  = (const float*)d_in[3];
    const float* Wk  = (const float*)d_in[4];
    const float* bk  = (const float*)d_in[5];
    const float* Wv  = (const float*)d_in[6];
    const float* bv  = (const float*)d_in[7];
    const float* Wo  = (const float*)d_in[8];
    const float* bo  = (const float*)d_in[9];
    const float* a1  = (const float*)d_in[10];
    const float* be1 = (const float*)d_in[11];
    const float* a2  = (const float*)d_in[12];
    const float* be2 = (const float*)d_in[13];
    const float* W1  = (const float*)d_in[14];
    const float* b1  = (const float*)d_in[15];
    const float* W2  = (const float*)d_in[16];
    const float* b2  = (const float*)d_in[17];
    const float* Wp  = (const float*)d_in[18];
    const float* bp  = (const float*)d_in[19];

    float* xo = (float*)d_out;                    // x: M_ x D_
    float* po = xo + (size_t)M_ * D_;             // p: M_ x P_

    float *xn, *xnr, *q, *k, *v, *ctx, *x2, *hb, *xr;
    float *wq, *wk, *wv, *wo, *w1, *w2, *wp, *pxr;
    cudaGetSymbolAddress((void**)&xn,  g_xn);
    cudaGetSymbolAddress((void**)&xnr, g_xnr);
    cudaGetSymbolAddress((void**)&q,   g_q);
    cudaGetSymbolAddress((void**)&k,   g_k);
    cudaGetSymbolAddress((void**)&v,   g_v);
    cudaGetSymbolAddress((void**)&ctx, g_ctx);
    cudaGetSymbolAddress((void**)&x2,  g_x2);
    cudaGetSymbolAddress((void**)&hb,  g_h);
    cudaGetSymbolAddress((void**)&xr,  g_xr);
    cudaGetSymbolAddress((void**)&wq,  g_wq);
    cudaGetSymbolAddress((void**)&wk,  g_wk);
    cudaGetSymbolAddress((void**)&wv,  g_wv);
    cudaGetSymbolAddress((void**)&wo,  g_wo);
    cudaGetSymbolAddress((void**)&w1,  g_w1);
    cudaGetSymbolAddress((void**)&w2,  g_w2);
    cudaGetSymbolAddress((void**)&wp,  g_wp);
    cudaGetSymbolAddress((void**)&pxr, g_px);

    cudaFuncSetAttribute(attn_kernel, cudaFuncAttributeMaxDynamicSharedMemorySize, ATTN_SMEM);
    cudaFuncSetAttribute(tc_gemm<false,true,false>, cudaFuncAttributeMaxDynamicSharedMemorySize, GEMM_SMEM);
    cudaFuncSetAttribute(tc_gemm<false,true,true>,  cudaFuncAttributeMaxDynamicSharedMemorySize, GEMM_SMEM);
    cudaFuncSetAttribute(tc_gemm<true,true,false>,  cudaFuncAttributeMaxDynamicSharedMemorySize, GEMM_SMEM);
    cudaFuncSetAttribute(tc_gemm<false,false,true>, cudaFuncAttributeMaxDynamicSharedMemorySize, GEMM_SMEM);

    // 0. pre-round weights + param_x to tf32
    round_kernel<<<(D_*D_)/1024, 256>>>(Wq, wq, D_*D_);
    round_kernel<<<(D_*D_)/1024, 256>>>(Wk, wk, D_*D_);
    round_kernel<<<(D_*D_)/1024, 256>>>(Wv, wv, D_*D_);
    round_kernel<<<(D_*D_)/1024, 256>>>(Wo, wo, D_*D_);
    round_kernel<<<(D_*DFF_)/1024, 256>>>(W1, w1, D_*DFF_);
    round_kernel<<<(DFF_*D_)/1024, 256>>>(W2, w2, DFF_*D_);
    round_kernel<<<((D_+P_)*P_)/1024, 256>>>(Wp, wp, (D_+P_)*P_);
    round_kernel<<<(M_*P_)/1024, 256>>>(px, pxr, M_*P_);

    // 1. xn = LN1(feature_x): exact -> xn (residual), rounded -> xnr (GEMM input)
    ln_kernel<<<M_, 256>>>(fx, a1, be1, xn, xnr);

    // 2. Q,K,V
    dim3 gQKV(D_/128, M_/128);
    tc_gemm<false,true,false><<<gQKV, 256, GEMM_SMEM>>>(xnr, wq, bq, nullptr, q, nullptr, M_, D_, D_);
    tc_gemm<false,true,false><<<gQKV, 256, GEMM_SMEM>>>(xnr, wk, bk, nullptr, k, nullptr, M_, D_, D_);
    tc_gemm<false,true,false><<<gQKV, 256, GEMM_SMEM>>>(xnr, wv, bv, nullptr, v, nullptr, M_, D_, D_);

    // 3. attention -> ctx (rounded in epilogue)
    attn_kernel<<<dim3(S_/64, H_, B_), 128, ATTN_SMEM>>>(q, k, v, ctx);

    // 4. x = xn + ctx@Wo + bo  (exact -> d_out)
    tc_gemm<false,true,true><<<gQKV, 256, GEMM_SMEM>>>(ctx, wo, bo, xn, xo, nullptr, M_, D_, D_);

    // 5. x2 = LN2(x), rounded only (GEMM input)
    ln_kernel<<<M_, 256>>>(xo, a2, be2, x2, x2);

    // 6. h = relu(x2@W1+b1) rounded; x = x + h@W2 + b2 (exact -> d_out, rounded -> xr)
    tc_gemm<true,true,false><<<dim3(DFF_/128, M_/128), 256, GEMM_SMEM>>>(x2, w1, b1, nullptr, hb, hb, M_, DFF_, D_);
    tc_gemm<false,true,true><<<gQKV, 256, GEMM_SMEM>>>(hb, w2, b2, xo, xo, xr, M_, D_, DFF_);

    // 7. p = x@Wp[:D] + param_x@Wp[D:] + bp
    dim3 gP(P_/128, M_/128);
    tc_gemm<false,true,false><<<gP, 256, GEMM_SMEM>>>(xr, wp, bp, nullptr, po, nullptr, M_, P_, D_);
    tc_gemm<false,false,true><<<gP, 256, GEMM_SMEM>>>(pxr, wp + (size_t)D_ * P_, nullptr, po, po, nullptr, M_, P_, P_);
}

// round 6
// speedup vs baseline: 6.0126x; 1.7929x over previous
#include <cuda_runtime.h>
#include <cuda_fp16.h>
#include <cstdint>

// ---------------- problem constants ----------------
#define B_  4
#define S_  2048
#define D_  1024
#define P_  256
#define H_  16
#define DH_ 64
#define DFF_ 512
#define M_  (B_*S_)           // 8192 rows
#define EPS_ 1e-6f

// ---------------- scratch (static device globals; no allocation) ----------------
__device__ float  g_xn [M_*D_];          // exact LN1 output (residual)
__device__ __half g_xnr[M_*D_];          // half LN1 output (GEMM A)
__device__ __half g_qh [M_*D_];
__device__ __half g_kh [M_*D_];
__device__ __half g_vh [M_*D_];
__device__ __half g_vt [M_*D_];          // V transposed: [(b*H+h)*64+d][S]
__device__ __half g_ctx[M_*D_];
__device__ __half g_x2 [M_*D_];
__device__ __half g_hb [M_*DFF_];
__device__ __half g_xr [M_*D_];          // half copy of final x (Wp input)
__device__ __half g_pxh[M_*P_];
__device__ __half g_wqT[D_*D_];
__device__ __half g_wkT[D_*D_];
__device__ __half g_wvT[D_*D_];
__device__ __half g_woT[D_*D_];
__device__ __half g_w1T[D_*DFF_];
__device__ __half g_w2T[DFF_*D_];
__device__ __half g_wpTt[P_*D_];
__device__ __half g_wpTb[P_*P_];

// ---------------- ptx helpers ----------------
__device__ __forceinline__ void mma_f16(float c[4], const uint32_t a[4], const uint32_t b[2]) {
    asm volatile(
        "mma.sync.aligned.m16n8k16.row.col.f32.f16.f16.f32 "
        "{%0,%1,%2,%3}, {%4,%5,%6,%7}, {%8,%9}, {%0,%1,%2,%3};\n"
        : "+f"(c[0]), "+f"(c[1]), "+f"(c[2]), "+f"(c[3])
        : "r"(a[0]), "r"(a[1]), "r"(a[2]), "r"(a[3]), "r"(b[0]), "r"(b[1]));
}

__device__ __forceinline__ uint32_t smem_u32(const void* p) {
    uint32_t a;
    asm("{ .reg .u64 t; cvta.to.shared.u64 t, %1; cvt.u32.u64 %0, t; }" : "=r"(a) : "l"(p));
    return a;
}

__device__ __forceinline__ void cp16(uint32_t dst, const void* src) {
    asm volatile("cp.async.ca.shared.global [%0], [%1], 16;" :: "r"(dst), "l"(src));
}
__device__ __forceinline__ void cp_commit() {
    asm volatile("cp.async.commit_group;" ::: "memory");
}
template<int N_>
__device__ __forceinline__ void cp_wait() {
    asm volatile("cp.async.wait_group %0;" :: "n"(N_) : "memory");
}

__device__ __forceinline__ uint32_t f2h2(float a, float b) {
    __half2 h = __floats2half2_rn(a, b);
    return *(uint32_t*)&h;
}

// ---------------- prep kernels ----------------
// transpose+convert weight: in[K][N] f32 -> out[N][K] half
__global__ void wtrans_kernel(const float* __restrict__ in, __half* __restrict__ out,
                              int K, int N) {
    __shared__ float tile[32][33];
    const int n0 = blockIdx.x*32, k0 = blockIdx.y*32;
    const int tx = threadIdx.x, ty = threadIdx.y;   // 32x8
    #pragma unroll
    for (int j = 0; j < 32; j += 8)
        tile[ty+j][tx] = in[(size_t)(k0+ty+j)*N + n0+tx];
    __syncthreads();
    #pragma unroll
    for (int j = 0; j < 32; j += 8)
        out[(size_t)(n0+ty+j)*K + k0+tx] = __float2half_rn(tile[tx][ty+j]);
}

__global__ void hconv_kernel(const float* __restrict__ in, __half* __restrict__ out, int n) {
    int i = (blockIdx.x * 256 + threadIdx.x) * 4;
    if (i < n) {
        float4 v = *(const float4*)(in + i);
        __half2* o2 = (__half2*)(out + i);
        o2[0] = __floats2half2_rn(v.x, v.y);
        o2[1] = __floats2half2_rn(v.z, v.w);
    }
}

// V transpose: v[b*S+s][D] half -> vt[((b*H+h)*64+d)][S] half
__global__ void vtrans_kernel(const __half* __restrict__ v, __half* __restrict__ vt) {
    __shared__ __half tile[32][33];
    const int d0 = blockIdx.x*32, s0 = blockIdx.y*32, b = blockIdx.z;
    const int tx = threadIdx.x, ty = threadIdx.y;   // 32x8
    #pragma unroll
    for (int j = 0; j < 32; j += 8)
        tile[ty+j][tx] = v[(size_t)(b*S_ + s0+ty+j)*D_ + d0+tx];
    __syncthreads();
    const int h = d0 >> 6, dr = d0 & 63;
    #pragma unroll
    for (int j = 0; j < 32; j += 8)
        vt[(size_t)((b*H_ + h)*64 + dr+ty+j)*S_ + s0+tx] = tile[tx][ty+j];
}

// ---------------- LayerNorm: optional exact f32 + half output ----------------
__global__ void ln_kernel(const float* __restrict__ in,
                          const float* __restrict__ alpha,
                          const float* __restrict__ beta,
                          float* __restrict__ out,      // exact (nullable)
                          __half* __restrict__ outh) {  // half
    const int row = blockIdx.x;
    const int t = threadIdx.x;            // 256 threads, 4 elems each
    const float* x = in + (size_t)row * D_;
    float v[4];
    float s = 0.f;
    #pragma unroll
    for (int i = 0; i < 4; i++) { v[i] = x[t + 256*i]; s += v[i]; }

    __shared__ float red[8];
    #pragma unroll
    for (int o = 16; o > 0; o >>= 1) s += __shfl_xor_sync(0xffffffffu, s, o);
    if ((t & 31) == 0) red[t >> 5] = s;
    __syncthreads();
    float tot = 0.f;
    #pragma unroll
    for (int i = 0; i < 8; i++) tot += red[i];
    const float mu = tot * (1.0f / D_);

    float ss = 0.f;
    #pragma unroll
    for (int i = 0; i < 4; i++) { float d = v[i] - mu; ss += d * d; }
    __syncthreads();
    #pragma unroll
    for (int o = 16; o > 0; o >>= 1) ss += __shfl_xor_sync(0xffffffffu, ss, o);
    if ((t & 31) == 0) red[t >> 5] = ss;
    __syncthreads();
    float sst = 0.f;
    #pragma unroll
    for (int i = 0; i < 8; i++) sst += red[i];

    const float stdv = sqrtf(fmaxf(sst, 0.f) * (1.0f / (D_ - 1)));
    const float inv = 1.0f / (stdv + EPS_);
    float*  o  = out  ? out  + (size_t)row * D_ : nullptr;
    __half* oh = outh + (size_t)row * D_;
    #pragma unroll
    for (int i = 0; i < 4; i++) {
        int c = t + 256*i;
        const float y = alpha[c] * (v[i] - mu) * inv + beta[c];
        oh[c] = __float2half_rn(y);
        if (o) o[c] = y;
    }
}

// ---------------- fp16 mma GEMM: 128x128x64 chunks, cp.async 3-stage ----------------
// A[M][K] half row-major, Bt[N][K] half (k-contiguous). Acc f32.
#define SWW 36                    // smem row stride in words (72 halves, 144B)
#define TILEH (128*72)            // halves per tile (A or B)
#define STGH  (2*TILEH)           // halves per stage
#define GEMM_SMEM (3*STGH*2)      // 110592 bytes

template<bool RELU, bool HASBIAS, bool HASRES>
__global__ __launch_bounds__(256, 2)
void hgemm(const __half* __restrict__ A, const __half* __restrict__ Bt,
           const float* __restrict__ bias, const float* __restrict__ res,
           float* __restrict__ C, __half* __restrict__ Ch,
           int M, int N, int K) {
    extern __shared__ __half hsm[];
    const uint32_t sb = smem_u32(hsm);
    const int t = threadIdx.x;
    const int w = t >> 5, lane = t & 31;
    const int wm = w >> 2, wn = w & 3;       // warp grid 2 (m) x 4 (n), warp tile 64x32
    const int g = lane >> 2, tg = lane & 3;
    const int bx = blockIdx.x, by = blockIdx.y;

    const __half* Ab = A  + (size_t)by * 128 * K;
    const __half* Bb = Bt + (size_t)bx * 128 * K;
    const int KT = K >> 6;   // K / 64

    // cp.async mapping: 1024 16B-chunks per tile, 4 per thread
    const int crow = t >> 1;                 // 0..127 (two chunks per row per j? no:)
    // chunk c = t + 256*j: row = c>>3 (0..127), c8 = c&7 (8 chunks of 16B per 128B row)

    // prologue: stages 0,1
    #pragma unroll
    for (int s = 0; s < 2; s++) {
        if (s < KT) {
            const uint32_t as = sb + (s*STGH)*2;
            const uint32_t bs = as + TILEH*2;
            #pragma unroll
            for (int j = 0; j < 4; j++) {
                const int c = t + 256*j;
                const int row = c >> 3, c8 = c & 7;
                cp16(as + (row*72 + c8*8)*2, Ab + (size_t)row*K + s*64 + c8*8);
                cp16(bs + (row*72 + c8*8)*2, Bb + (size_t)row*K + s*64 + c8*8);
            }
        }
        cp_commit();
    }
    (void)crow;

    float acc[4][4][4];
    #pragma unroll
    for (int mi = 0; mi < 4; mi++)
        #pragma unroll
        for (int ni = 0; ni < 4; ni++)
            #pragma unroll
            for (int r = 0; r < 4; r++) acc[mi][ni][r] = 0.f;

    for (int kt = 0; kt < KT; kt++) {
        cp_wait<1>();
        __syncthreads();

        // prefetch stage kt+2
        if (kt + 2 < KT) {
            const int s = (kt + 2) % 3;
            const uint32_t as = sb + (s*STGH)*2;
            const uint32_t bs = as + TILEH*2;
            #pragma unroll
            for (int j = 0; j < 4; j++) {
                const int c = t + 256*j;
                const int row = c >> 3, c8 = c & 7;
                cp16(as + (row*72 + c8*8)*2, Ab + (size_t)row*K + (kt+2)*64 + c8*8);
                cp16(bs + (row*72 + c8*8)*2, Bb + (size_t)row*K + (kt+2)*64 + c8*8);
            }
        }
        cp_commit();

        // compute on stage kt%3: 4 k16-steps
        const int cs = kt % 3;
        const uint32_t* Au = (const uint32_t*)(hsm + cs*STGH);
        const uint32_t* Bu = (const uint32_t*)(hsm + cs*STGH + TILEH);
        #pragma unroll
        for (int kk = 0; kk < 4; kk++) {
            uint32_t af[4][4];
            #pragma unroll
            for (int mi = 0; mi < 4; mi++) {
                const int base = (wm*64 + mi*16 + g)*SWW + kk*8 + tg;
                af[mi][0] = Au[base];
                af[mi][1] = Au[base + 8*SWW];
                af[mi][2] = Au[base + 4];
                af[mi][3] = Au[base + 8*SWW + 4];
            }
            uint32_t bf[4][2];
            #pragma unroll
            for (int ni = 0; ni < 4; ni++) {
                const int base = (wn*32 + ni*8 + g)*SWW + kk*8 + tg;
                bf[ni][0] = Bu[base];
                bf[ni][1] = Bu[base + 4];
            }
            #pragma unroll
            for (int mi = 0; mi < 4; mi++)
                #pragma unroll
                for (int ni = 0; ni < 4; ni++)
                    mma_f16(acc[mi][ni], af[mi], bf[ni]);
        }
    }

    // epilogue
    #pragma unroll
    for (int mi = 0; mi < 4; mi++) {
        #pragma unroll
        for (int ni = 0; ni < 4; ni++) {
            const size_t row0 = (size_t)by*128 + wm*64 + mi*16 + g;
            const size_t row1 = row0 + 8;
            const int col = bx*128 + wn*32 + ni*8 + 2*tg;
            float v0 = acc[mi][ni][0], v1 = acc[mi][ni][1];
            float v2 = acc[mi][ni][2], v3 = acc[mi][ni][3];
            if (HASBIAS) {
                const float bb0 = bias[col], bb1 = bias[col+1];
                v0 += bb0; v1 += bb1; v2 += bb0; v3 += bb1;
            }
            if (HASRES) {
                v0 += res[row0*N + col]; v1 += res[row0*N + col + 1];
                v2 += res[row1*N + col]; v3 += res[row1*N + col + 1];
            }
            if (RELU) {
                v0 = fmaxf(v0, 0.f); v1 = fmaxf(v1, 0.f);
                v2 = fmaxf(v2, 0.f); v3 = fmaxf(v3, 0.f);
            }
            if (Ch) {
                *(__half2*)&Ch[row0*N + col] = __floats2half2_rn(v0, v1);
                *(__half2*)&Ch[row1*N + col] = __floats2half2_rn(v2, v3);
            }
            if (C) {
                *(float2*)&C[row0*N + col] = make_float2(v0, v1);
                *(float2*)&C[row1*N + col] = make_float2(v2, v3);
            }
        }
    }
}

// ---------------- fp16 flash attention ----------------
// 128 threads (4 warps), 64 queries/CTA (16 rows/warp), 64-key tiles, dh=64.
// Smem tiles [64][72 halves] (stride 36 words).
#define ATTN_SMEM (3 * 64 * 72 * 2)    // 27648 B

__global__ __launch_bounds__(128, 4)
void attn_kernel(const __half* __restrict__ Q, const __half* __restrict__ K,
                 const __half* __restrict__ Vt, __half* __restrict__ O) {
    extern __shared__ __half smh[];
    __half* Ks = smh;                 // [64][72]
    __half* Vs = Ks + 64*72;          // [64][72]  (rows = dh, cols = keys)
    __half* Ps = Vs + 64*72;          // [64][72]  (also Q staging)

    const int qt = blockIdx.x, h = blockIdx.y, b = blockIdx.z;
    const int t = threadIdx.x;
    const int wq = t >> 5, lane = t & 31;
    const int g = lane >> 2, tg = lane & 3;

    // ---- stage Q tile into Ps ----
    #pragma unroll
    for (int i = 0; i < 4; i++) {
        const int c = t + 128*i;        // 512 chunks of 16B
        const int row = c >> 3, c8 = c & 7;
        *(uint4*)(Ps + row*72 + c8*8) =
            *(const uint4*)(Q + ((size_t)(b*S_ + qt*64 + row))*D_ + h*DH_ + c8*8);
    }
    __syncthreads();

    // ---- preload Q fragments (warp rows wq*16..+15), 4 k16-steps ----
    uint32_t aQ[4][4];
    {
        const uint32_t* Pu = (const uint32_t*)Ps;
        #pragma unroll
        for (int kk = 0; kk < 4; kk++) {
            const int base = (wq*16 + g)*SWW + kk*8 + tg;
            aQ[kk][0] = Pu[base];
            aQ[kk][1] = Pu[base + 8*SWW];
            aQ[kk][2] = Pu[base + 4];
            aQ[kk][3] = Pu[base + 8*SWW + 4];
        }
    }

    float m[2], l[2], o[8][4];
    m[0] = m[1] = -1e30f; l[0] = l[1] = 0.f;
    #pragma unroll
    for (int ni = 0; ni < 8; ni++)
        #pragma unroll
        for (int r = 0; r < 4; r++) o[ni][r] = 0.f;

    const __half* Vrow = Vt + (size_t)((b*H_ + h)*64) * S_;

    for (int kt = 0; kt < S_/64; kt++) {
        __syncthreads();
        // K tile: [key][dh], V tile: [dh][keys]
        #pragma unroll
        for (int i = 0; i < 4; i++) {
            const int c = t + 128*i;
            const int row = c >> 3, c8 = c & 7;
            *(uint4*)(Ks + row*72 + c8*8) =
                *(const uint4*)(K + ((size_t)(b*S_ + kt*64 + row))*D_ + h*DH_ + c8*8);
            *(uint4*)(Vs + row*72 + c8*8) =
                *(const uint4*)(Vrow + (size_t)row*S_ + kt*64 + c8*8);
        }
        __syncthreads();

        // ---- S = Q K^T ----
        float acc[8][4];
        #pragma unroll
        for (int ni = 0; ni < 8; ni++)
            #pragma unroll
            for (int r = 0; r < 4; r++) acc[ni][r] = 0.f;

        const uint32_t* Ku = (const uint32_t*)Ks;
        #pragma unroll
        for (int kk = 0; kk < 4; kk++) {
            #pragma unroll
            for (int ni = 0; ni < 8; ni++) {
                uint32_t bf[2];
                const int base = (ni*8 + g)*SWW + kk*8 + tg;
                bf[0] = Ku[base];
                bf[1] = Ku[base + 4];
                mma_f16(acc[ni], aQ[kk], bf);
            }
        }

        // ---- online softmax (rows g, g+8 of warp slice) ----
        #pragma unroll
        for (int ni = 0; ni < 8; ni++)
            #pragma unroll
            for (int r = 0; r < 4; r++) acc[ni][r] *= 0.125f;

        float tm0 = -1e30f, tm1 = -1e30f;
        #pragma unroll
        for (int ni = 0; ni < 8; ni++) {
            tm0 = fmaxf(tm0, fmaxf(acc[ni][0], acc[ni][1]));
            tm1 = fmaxf(tm1, fmaxf(acc[ni][2], acc[ni][3]));
        }
        #pragma unroll
        for (int off = 1; off < 4; off <<= 1) {
            tm0 = fmaxf(tm0, __shfl_xor_sync(0xffffffffu, tm0, off));
            tm1 = fmaxf(tm1, __shfl_xor_sync(0xffffffffu, tm1, off));
        }
        const float mn0 = fmaxf(m[0], tm0);
        const float mn1 = fmaxf(m[1], tm1);
        const float corr0 = __expf(m[0] - mn0);
        const float corr1 = __expf(m[1] - mn1);
        float ts0 = 0.f, ts1 = 0.f;
        #pragma unroll
        for (int ni = 0; ni < 8; ni++) {
            acc[ni][0] = __expf(acc[ni][0] - mn0);
            acc[ni][1] = __expf(acc[ni][1] - mn0);
            acc[ni][2] = __expf(acc[ni][2] - mn1);
            acc[ni][3] = __expf(acc[ni][3] - mn1);
            ts0 += acc[ni][0] + acc[ni][1];
            ts1 += acc[ni][2] + acc[ni][3];
        }
        #pragma unroll
        for (int off = 1; off < 4; off <<= 1) {
            ts0 += __shfl_xor_sync(0xffffffffu, ts0, off);
            ts1 += __shfl_xor_sync(0xffffffffu, ts1, off);
        }
        l[0] = l[0]*corr0 + ts0;  m[0] = mn0;
        l[1] = l[1]*corr1 + ts1;  m[1] = mn1;
        #pragma unroll
        for (int ni = 0; ni < 8; ni++) {
            o[ni][0] *= corr0; o[ni][1] *= corr0;
            o[ni][2] *= corr1; o[ni][3] *= corr1;
        }

        // ---- store P (half) to warp-private smem slice ----
        {
            uint32_t* Psu = (uint32_t*)Ps;
            #pragma unroll
            for (int ni = 0; ni < 8; ni++) {
                Psu[(wq*16 + g    )*SWW + ni*4 + tg] = f2h2(acc[ni][0], acc[ni][1]);
                Psu[(wq*16 + g + 8)*SWW + ni*4 + tg] = f2h2(acc[ni][2], acc[ni][3]);
            }
        }
        __syncwarp();

        // ---- O += P V  (A = P [m][key], B = Vs [dh][key] col-major frag) ----
        const uint32_t* Pu = (const uint32_t*)Ps;
        const uint32_t* Vu = (const uint32_t*)Vs;
        #pragma unroll
        for (int kk = 0; kk < 4; kk++) {
            uint32_t aP[4];
            const int pbase = (wq*16 + g)*SWW + kk*8 + tg;
            aP[0] = Pu[pbase];
            aP[1] = Pu[pbase + 8*SWW];
            aP[2] = Pu[pbase + 4];
            aP[3] = Pu[pbase + 8*SWW + 4];
            #pragma unroll
            for (int ni = 0; ni < 8; ni++) {
                uint32_t bf[2];
                const int vbase = (ni*8 + g)*SWW + kk*8 + tg;
                bf[0] = Vu[vbase];
                bf[1] = Vu[vbase + 4];
                mma_f16(o[ni], aP, bf);
            }
        }
    }

    // ---- epilogue: O /= l, write half ctx ----
    const float inv0 = 1.0f / l[0];
    const float inv1 = 1.0f / l[1];
    const size_t row0 = (size_t)(b*S_ + qt*64 + wq*16 + g);
    const size_t row1 = row0 + 8;
    #pragma unroll
    for (int ni = 0; ni < 8; ni++) {
        const int col = ni*8 + 2*tg;
        *(__half2*)&O[row0*D_ + h*DH_ + col] = __floats2half2_rn(o[ni][0]*inv0, o[ni][1]*inv0);
        *(__half2*)&O[row1*D_ + h*DH_ + col] = __floats2half2_rn(o[ni][2]*inv1, o[ni][3]*inv1);
    }
}

// ---------------- host launcher ----------------
extern "C" void kernel_launch(void* const* d_in, const int* in_sizes, int n_in,
                              void* d_out, int out_size) {
    const float* fx  = (const float*)d_in[0];
    const float* px  = (const float*)d_in[1];
    const float* Wq  = (const float*)d_in[2];
    const float* bq  = (const float*)d_in[3];
    const float* Wk  = (const float*)d_in[4];
    const float* bk  = (const float*)d_in[5];
    const float* Wv  = (const float*)d_in[6];
    const float* bv  = (const float*)d_in[7];
    const float* Wo  = (const float*)d_in[8];
    const float* bo  = (const float*)d_in[9];
    const float* a1  = (const float*)d_in[10];
    const float* be1 = (const float*)d_in[11];
    const float* a2  = (const float*)d_in[12];
    const float* be2 = (const float*)d_in[13];
    const float* W1  = (const float*)d_in[14];
    const float* b1  = (const float*)d_in[15];
    const float* W2  = (const float*)d_in[16];
    const float* b2  = (const float*)d_in[17];
    const float* Wp  = (const float*)d_in[18];
    const float* bp  = (const float*)d_in[19];

    float* xo = (float*)d_out;                    // x: M_ x D_
    float* po = xo + (size_t)M_ * D_;             // p: M_ x P_

    float  *xn;
    __half *xnr, *qh, *kh, *vh, *vt, *ctx, *x2h, *hbh, *xrh, *pxh;
    __half *wqT, *wkT, *wvT, *woT, *w1T, *w2T, *wpTt, *wpTb;
    cudaGetSymbolAddress((void**)&xn,   g_xn);
    cudaGetSymbolAddress((void**)&xnr,  g_xnr);
    cudaGetSymbolAddress((void**)&qh,   g_qh);
    cudaGetSymbolAddress((void**)&kh,   g_kh);
    cudaGetSymbolAddress((void**)&vh,   g_vh);
    cudaGetSymbolAddress((void**)&vt,   g_vt);
    cudaGetSymbolAddress((void**)&ctx,  g_ctx);
    cudaGetSymbolAddress((void**)&x2h,  g_x2);
    cudaGetSymbolAddress((void**)&hbh,  g_hb);
    cudaGetSymbolAddress((void**)&xrh,  g_xr);
    cudaGetSymbolAddress((void**)&pxh,  g_pxh);
    cudaGetSymbolAddress((void**)&wqT,  g_wqT);
    cudaGetSymbolAddress((void**)&wkT,  g_wkT);
    cudaGetSymbolAddress((void**)&wvT,  g_wvT);
    cudaGetSymbolAddress((void**)&woT,  g_woT);
    cudaGetSymbolAddress((void**)&w1T,  g_w1T);
    cudaGetSymbolAddress((void**)&w2T,  g_w2T);
    cudaGetSymbolAddress((void**)&wpTt, g_wpTt);
    cudaGetSymbolAddress((void**)&wpTb, g_wpTb);

    cudaFuncSetAttribute(attn_kernel, cudaFuncAttributeMaxDynamicSharedMemorySize, ATTN_SMEM);
    cudaFuncSetAttribute(hgemm<false,true,false>, cudaFuncAttributeMaxDynamicSharedMemorySize, GEMM_SMEM);
    cudaFuncSetAttribute(hgemm<false,true,true>,  cudaFuncAttributeMaxDynamicSharedMemorySize, GEMM_SMEM);
    cudaFuncSetAttribute(hgemm<true,true,false>,  cudaFuncAttributeMaxDynamicSharedMemorySize, GEMM_SMEM);
    cudaFuncSetAttribute(hgemm<false,false,true>, cudaFuncAttributeMaxDynamicSharedMemorySize, GEMM_SMEM);

    // 0. weight transposes + conversions
    dim3 tb(32, 8);
    wtrans_kernel<<<dim3(D_/32,  D_/32),  tb>>>(Wq, wqT, D_, D_);
    wtrans_kernel<<<dim3(D_/32,  D_/32),  tb>>>(Wk, wkT, D_, D_);
    wtrans_kernel<<<dim3(D_/32,  D_/32),  tb>>>(Wv, wvT, D_, D_);
    wtrans_kernel<<<dim3(D_/32,  D_/32),  tb>>>(Wo, woT, D_, D_);
    wtrans_kernel<<<dim3(DFF_/32, D_/32), tb>>>(W1, w1T, D_, DFF_);
    wtrans_kernel<<<dim3(D_/32, DFF_/32), tb>>>(W2, w2T, DFF_, D_);
    wtrans_kernel<<<dim3(P_/32,  D_/32),  tb>>>(Wp, wpTt, D_, P_);
    wtrans_kernel<<<dim3(P_/32,  P_/32),  tb>>>(Wp + (size_t)D_*P_, wpTb, P_, P_);
    hconv_kernel<<<(M_*P_)/1024, 256>>>(px, pxh, M_*P_);

    // 1. xn = LN1(feature_x): exact -> xn, half -> xnr
    ln_kernel<<<M_, 256>>>(fx, a1, be1, xn, xnr);

    // 2. Q,K,V (half outputs)
    dim3 gQKV(D_/128, M_/128);
    hgemm<false,true,false><<<gQKV, 256, GEMM_SMEM>>>(xnr, wqT, bq, nullptr, nullptr, qh, M_, D_, D_);
    hgemm<false,true,false><<<gQKV, 256, GEMM_SMEM>>>(xnr, wkT, bk, nullptr, nullptr, kh, M_, D_, D_);
    hgemm<false,true,false><<<gQKV, 256, GEMM_SMEM>>>(xnr, wvT, bv, nullptr, nullptr, vh, M_, D_, D_);

    // 2b. transpose V for PV mma
    vtrans_kernel<<<dim3(D_/32, S_/32, B_), tb>>>(vh, vt);

    // 3. attention -> ctx (half)
    attn_kernel<<<dim3(S_/64, H_, B_), 128, ATTN_SMEM>>>(qh, kh, vt, ctx);

    // 4. x = xn + ctx@Wo + bo (f32 -> d_out)
    hgemm<false,true,true><<<gQKV, 256, GEMM_SMEM>>>(ctx, woT, bo, xn, xo, nullptr, M_, D_, D_);

    // 5. x2 = LN2(x) (half only)
    ln_kernel<<<M_, 256>>>(xo, a2, be2, nullptr, x2h);

    // 6. h = relu(x2@W1+b1) (half); x = x + h@W2 + b2 (f32 -> d_out, half -> xrh)
    hgemm<true,true,false><<<dim3(DFF_/128, M_/128), 256, GEMM_SMEM>>>(x2h, w1T, b1, nullptr, nullptr, hbh, M_, DFF_, D_);
    hgemm<false,true,true><<<gQKV, 256, GEMM_SMEM>>>(hbh, w2T, b2, xo, xo, xrh, M_, D_, DFF_);

    // 7. p = x@Wp[:D] + param_x@Wp[D:] + bp
    dim3 gP(P_/128, M_/128);
    hgemm<false,true,false><<<gP, 256, GEMM_SMEM>>>(xrh, wpTt, bp, nullptr, po, nullptr, M_, P_, D_);
    hgemm<false,false,true><<<gP, 256, GEMM_SMEM>>>(pxh, wpTb, nullptr, po, po, nullptr, M_, P_, P_);
}

// round 7
// speedup vs baseline: 6.3372x; 1.0540x over previous
#include <cuda_runtime.h>
#include <cuda_fp16.h>
#include <cstdint>

// ---------------- problem constants ----------------
#define B_  4
#define S_  2048
#define D_  1024
#define P_  256
#define H_  16
#define DH_ 64
#define DFF_ 512
#define M_  (B_*S_)           // 8192 rows
#define EPS_ 1e-6f

// ---------------- scratch (static device globals; no allocation) ----------------
__device__ float  g_xn [M_*D_];          // exact LN1 output (residual)
__device__ __half g_xnr[M_*D_];          // half LN1 output (GEMM A)
__device__ __half g_qkv[M_*3*D_];        // fused QKV output [M][3072]
__device__ __half g_vt [M_*D_];          // V transposed: [(b*H+h)*64+d][S]
__device__ __half g_ctx[M_*D_];
__device__ __half g_x2 [M_*D_];
__device__ __half g_hb [M_*DFF_];
__device__ __half g_xr [M_*D_];          // half copy of final x (Wp input)
__device__ __half g_pxh[M_*P_];
__device__ __half g_wqkvT[3*D_*D_];      // [3072][1024]
__device__ __half g_woT[D_*D_];
__device__ __half g_w1T[D_*DFF_];
__device__ __half g_w2T[DFF_*D_];
__device__ __half g_wpT[P_*(D_+P_)];     // [256][1280]
__device__ float  g_bqkv[3*D_];

// ---------------- ptx helpers ----------------
__device__ __forceinline__ void mma_f16(float c[4], const uint32_t a[4], const uint32_t b[2]) {
    asm volatile(
        "mma.sync.aligned.m16n8k16.row.col.f32.f16.f16.f32 "
        "{%0,%1,%2,%3}, {%4,%5,%6,%7}, {%8,%9}, {%0,%1,%2,%3};\n"
        : "+f"(c[0]), "+f"(c[1]), "+f"(c[2]), "+f"(c[3])
        : "r"(a[0]), "r"(a[1]), "r"(a[2]), "r"(a[3]), "r"(b[0]), "r"(b[1]));
}

__device__ __forceinline__ uint32_t smem_u32(const void* p) {
    uint32_t a;
    asm("{ .reg .u64 t; cvta.to.shared.u64 t, %1; cvt.u32.u64 %0, t; }" : "=r"(a) : "l"(p));
    return a;
}

__device__ __forceinline__ void cp16(uint32_t dst, const void* src) {
    asm volatile("cp.async.ca.shared.global [%0], [%1], 16;" :: "r"(dst), "l"(src));
}
__device__ __forceinline__ void cp_commit() {
    asm volatile("cp.async.commit_group;" ::: "memory");
}
template<int N_>
__device__ __forceinline__ void cp_wait() {
    asm volatile("cp.async.wait_group %0;" :: "n"(N_) : "memory");
}

__device__ __forceinline__ uint32_t f2h2(float a, float b) {
    __half2 h = __floats2half2_rn(a, b);
    return *(uint32_t*)&h;
}

// ---------------- prep kernels ----------------
// transpose+convert weight: in[K][N] f32 -> out[N][K] half
__global__ void wtrans_kernel(const float* __restrict__ in, __half* __restrict__ out,
                              int K, int N) {
    __shared__ float tile[32][33];
    const int n0 = blockIdx.x*32, k0 = blockIdx.y*32;
    const int tx = threadIdx.x, ty = threadIdx.y;   // 32x8
    #pragma unroll
    for (int j = 0; j < 32; j += 8)
        tile[ty+j][tx] = in[(size_t)(k0+ty+j)*N + n0+tx];
    __syncthreads();
    #pragma unroll
    for (int j = 0; j < 32; j += 8)
        out[(size_t)(n0+ty+j)*K + k0+tx] = __float2half_rn(tile[tx][ty+j]);
}

__global__ void hconv_kernel(const float* __restrict__ in, __half* __restrict__ out, int n) {
    int i = (blockIdx.x * 256 + threadIdx.x) * 4;
    if (i < n) {
        float4 v = *(const float4*)(in + i);
        __half2* o2 = (__half2*)(out + i);
        o2[0] = __floats2half2_rn(v.x, v.y);
        o2[1] = __floats2half2_rn(v.z, v.w);
    }
}

__global__ void bcat_kernel(const float* __restrict__ bq, const float* __restrict__ bk,
                            const float* __restrict__ bv, float* __restrict__ out) {
    int i = blockIdx.x*256 + threadIdx.x;
    out[i] = (i < D_) ? bq[i] : (i < 2*D_) ? bk[i - D_] : bv[i - 2*D_];
}

// V transpose: qkvV[b*S+s][stride 3072] half -> vt[((b*H+h)*64+d)][S] half
__global__ void vtrans_kernel(const __half* __restrict__ v, __half* __restrict__ vt) {
    __shared__ __half tile[32][33];
    const int d0 = blockIdx.x*32, s0 = blockIdx.y*32, b = blockIdx.z;
    const int tx = threadIdx.x, ty = threadIdx.y;   // 32x8
    #pragma unroll
    for (int j = 0; j < 32; j += 8)
        tile[ty+j][tx] = v[(size_t)(b*S_ + s0+ty+j)*(3*D_) + d0+tx];
    __syncthreads();
    const int h = d0 >> 6, dr = d0 & 63;
    #pragma unroll
    for (int j = 0; j < 32; j += 8)
        vt[(size_t)((b*H_ + h)*64 + dr+ty+j)*S_ + s0+tx] = tile[tx][ty+j];
}

// ---------------- LayerNorm: optional exact f32 + half output ----------------
__global__ void ln_kernel(const float* __restrict__ in,
                          const float* __restrict__ alpha,
                          const float* __restrict__ beta,
                          float* __restrict__ out,      // exact (nullable)
                          __half* __restrict__ outh) {  // half
    const int row = blockIdx.x;
    const int t = threadIdx.x;            // 256 threads, 4 elems each
    const float* x = in + (size_t)row * D_;
    float v[4];
    float s = 0.f;
    #pragma unroll
    for (int i = 0; i < 4; i++) { v[i] = x[t + 256*i]; s += v[i]; }

    __shared__ float red[8];
    #pragma unroll
    for (int o = 16; o > 0; o >>= 1) s += __shfl_xor_sync(0xffffffffu, s, o);
    if ((t & 31) == 0) red[t >> 5] = s;
    __syncthreads();
    float tot = 0.f;
    #pragma unroll
    for (int i = 0; i < 8; i++) tot += red[i];
    const float mu = tot * (1.0f / D_);

    float ss = 0.f;
    #pragma unroll
    for (int i = 0; i < 4; i++) { float d = v[i] - mu; ss += d * d; }
    __syncthreads();
    #pragma unroll
    for (int o = 16; o > 0; o >>= 1) ss += __shfl_xor_sync(0xffffffffu, ss, o);
    if ((t & 31) == 0) red[t >> 5] = ss;
    __syncthreads();
    float sst = 0.f;
    #pragma unroll
    for (int i = 0; i < 8; i++) sst += red[i];

    const float stdv = sqrtf(fmaxf(sst, 0.f) * (1.0f / (D_ - 1)));
    const float inv = 1.0f / (stdv + EPS_);
    float*  o  = out  ? out  + (size_t)row * D_ : nullptr;
    __half* oh = outh + (size_t)row * D_;
    #pragma unroll
    for (int i = 0; i < 4; i++) {
        int c = t + 256*i;
        const float y = alpha[c] * (v[i] - mu) * inv + beta[c];
        oh[c] = __float2half_rn(y);
        if (o) o[c] = y;
    }
}

// ---------------- fp16 mma GEMM: 128x128x64 chunks, cp.async 3-stage ----------------
// A[M][K1] + optional A2[M][K2] (concatenated along K); Bt[N][K1+K2] k-contiguous.
#define SWW 36                    // smem row stride in words (72 halves, 144B)
#define TILEH (128*72)            // halves per tile (A or B)
#define STGH  (2*TILEH)           // halves per stage
#define GEMM_SMEM (3*STGH*2)      // 110592 bytes

template<bool RELU, bool HASBIAS, bool HASRES>
__global__ __launch_bounds__(256, 2)
void hgemm(const __half* __restrict__ A, int K1,
           const __half* __restrict__ A2, int K2,
           const __half* __restrict__ Bt,
           const float* __restrict__ bias, const float* __restrict__ res,
           float* __restrict__ C, __half* __restrict__ Ch,
           int M, int N) {
    extern __shared__ __half hsm[];
    const uint32_t sb = smem_u32(hsm);
    const int t = threadIdx.x;
    const int w = t >> 5, lane = t & 31;
    const int wm = w >> 2, wn = w & 3;       // warp grid 2 (m) x 4 (n), warp tile 64x32
    const int g = lane >> 2, tg = lane & 3;
    const int bx = blockIdx.x, by = blockIdx.y;

    const int KB = K1 + K2;
    const int KT = KB >> 6, K1T = K1 >> 6;
    const __half* Ab  = A  + (size_t)by * 128 * K1;
    const __half* A2b = A2 ? A2 + (size_t)by * 128 * K2 : Ab;
    const __half* Bb  = Bt + (size_t)bx * 128 * KB;

    // prologue: stages 0,1
    #pragma unroll
    for (int s = 0; s < 2; s++) {
        const uint32_t as = sb + (s*STGH)*2;
        const uint32_t bs = as + TILEH*2;
        #pragma unroll
        for (int j = 0; j < 4; j++) {
            const int c = t + 256*j;
            const int row = c >> 3, c8 = c & 7;
            const __half* asrc = (s < K1T) ? Ab + (size_t)row*K1 + s*64 + c8*8
                                           : A2b + (size_t)row*K2 + (s - K1T)*64 + c8*8;
            cp16(as + (row*72 + c8*8)*2, asrc);
            cp16(bs + (row*72 + c8*8)*2, Bb + (size_t)row*KB + s*64 + c8*8);
        }
        cp_commit();
    }

    float acc[4][4][4];
    #pragma unroll
    for (int mi = 0; mi < 4; mi++)
        #pragma unroll
        for (int ni = 0; ni < 4; ni++)
            #pragma unroll
            for (int r = 0; r < 4; r++) acc[mi][ni][r] = 0.f;

    for (int kt = 0; kt < KT; kt++) {
        cp_wait<1>();
        __syncthreads();

        if (kt + 2 < KT) {
            const int kc = kt + 2;
            const int s = kc % 3;
            const uint32_t as = sb + (s*STGH)*2;
            const uint32_t bs = as + TILEH*2;
            #pragma unroll
            for (int j = 0; j < 4; j++) {
                const int c = t + 256*j;
                const int row = c >> 3, c8 = c & 7;
                const __half* asrc = (kc < K1T) ? Ab + (size_t)row*K1 + kc*64 + c8*8
                                                : A2b + (size_t)row*K2 + (kc - K1T)*64 + c8*8;
                cp16(as + (row*72 + c8*8)*2, asrc);
                cp16(bs + (row*72 + c8*8)*2, Bb + (size_t)row*KB + kc*64 + c8*8);
            }
        }
        cp_commit();

        const int cs = kt % 3;
        const uint32_t* Au = (const uint32_t*)(hsm + cs*STGH);
        const uint32_t* Bu = (const uint32_t*)(hsm + cs*STGH + TILEH);
        #pragma unroll
        for (int kk = 0; kk < 4; kk++) {
            uint32_t af[4][4];
            #pragma unroll
            for (int mi = 0; mi < 4; mi++) {
                const int base = (wm*64 + mi*16 + g)*SWW + kk*8 + tg;
                af[mi][0] = Au[base];
                af[mi][1] = Au[base + 8*SWW];
                af[mi][2] = Au[base + 4];
                af[mi][3] = Au[base + 8*SWW + 4];
            }
            uint32_t bf[4][2];
            #pragma unroll
            for (int ni = 0; ni < 4; ni++) {
                const int base = (wn*32 + ni*8 + g)*SWW + kk*8 + tg;
                bf[ni][0] = Bu[base];
                bf[ni][1] = Bu[base + 4];
            }
            #pragma unroll
            for (int mi = 0; mi < 4; mi++)
                #pragma unroll
                for (int ni = 0; ni < 4; ni++)
                    mma_f16(acc[mi][ni], af[mi], bf[ni]);
        }
    }

    // epilogue
    #pragma unroll
    for (int mi = 0; mi < 4; mi++) {
        #pragma unroll
        for (int ni = 0; ni < 4; ni++) {
            const size_t row0 = (size_t)by*128 + wm*64 + mi*16 + g;
            const size_t row1 = row0 + 8;
            const int col = bx*128 + wn*32 + ni*8 + 2*tg;
            float v0 = acc[mi][ni][0], v1 = acc[mi][ni][1];
            float v2 = acc[mi][ni][2], v3 = acc[mi][ni][3];
            if (HASBIAS) {
                const float bb0 = bias[col], bb1 = bias[col+1];
                v0 += bb0; v1 += bb1; v2 += bb0; v3 += bb1;
            }
            if (HASRES) {
                v0 += res[row0*N + col]; v1 += res[row0*N + col + 1];
                v2 += res[row1*N + col]; v3 += res[row1*N + col + 1];
            }
            if (RELU) {
                v0 = fmaxf(v0, 0.f); v1 = fmaxf(v1, 0.f);
                v2 = fmaxf(v2, 0.f); v3 = fmaxf(v3, 0.f);
            }
            if (Ch) {
                *(__half2*)&Ch[row0*N + col] = __floats2half2_rn(v0, v1);
                *(__half2*)&Ch[row1*N + col] = __floats2half2_rn(v2, v3);
            }
            if (C) {
                *(float2*)&C[row0*N + col] = make_float2(v0, v1);
                *(float2*)&C[row1*N + col] = make_float2(v2, v3);
            }
        }
    }
}

// ---------------- fp16 flash attention: 256 threads (8 warps), 128 queries/CTA ----------------
// K/V tiles 64 keys; Q/P region [128][72]; K,V [64][72].
#define ATTN_SMEM ((128 + 64 + 64) * 72 * 2)   // 36864 B

__global__ __launch_bounds__(256, 2)
void attn_kernel(const __half* __restrict__ QKV, const __half* __restrict__ Vt,
                 __half* __restrict__ O) {
    extern __shared__ __half smh[];
    __half* Ks = smh;                 // [64][72]
    __half* Vs = Ks + 64*72;          // [64][72]  (rows = dh, cols = keys)
    __half* Ps = Vs + 64*72;          // [128][72] (Q staging, then P)

    const int qt = blockIdx.x, h = blockIdx.y, b = blockIdx.z;
    const int t = threadIdx.x;
    const int wq = t >> 5, lane = t & 31;
    const int g = lane >> 2, tg = lane & 3;

    const __half* Qp = QKV + (size_t)h*DH_;                    // stride 3*D_
    const __half* Kp = QKV + D_ + (size_t)h*DH_;
    const __half* Vrow = Vt + (size_t)((b*H_ + h)*64) * S_;

    // ---- stage Q tile [128][64] into Ps ----
    #pragma unroll
    for (int i = 0; i < 4; i++) {
        const int c = t + 256*i;        // 1024 chunks of 16B
        const int row = c >> 3, c8 = c & 7;
        *(uint4*)(Ps + row*72 + c8*8) =
            *(const uint4*)(Qp + ((size_t)(b*S_ + qt*128 + row))*(3*D_) + c8*8);
    }
    __syncthreads();

    // ---- preload Q fragments (warp rows wq*16..+15), 4 k16-steps ----
    uint32_t aQ[4][4];
    {
        const uint32_t* Pu = (const uint32_t*)Ps;
        #pragma unroll
        for (int kk = 0; kk < 4; kk++) {
            const int base = (wq*16 + g)*SWW + kk*8 + tg;
            aQ[kk][0] = Pu[base];
            aQ[kk][1] = Pu[base + 8*SWW];
            aQ[kk][2] = Pu[base + 4];
            aQ[kk][3] = Pu[base + 8*SWW + 4];
        }
    }

    float m[2], l[2], o[8][4];
    m[0] = m[1] = -1e30f; l[0] = l[1] = 0.f;
    #pragma unroll
    for (int ni = 0; ni < 8; ni++)
        #pragma unroll
        for (int r = 0; r < 4; r++) o[ni][r] = 0.f;

    for (int kt = 0; kt < S_/64; kt++) {
        __syncthreads();
        // K tile [64 keys][64 dh], V tile [64 dh][64 keys]: 512 chunks each
        #pragma unroll
        for (int i = 0; i < 2; i++) {
            const int c = t + 256*i;
            const int row = c >> 3, c8 = c & 7;
            *(uint4*)(Ks + row*72 + c8*8) =
                *(const uint4*)(Kp + ((size_t)(b*S_ + kt*64 + row))*(3*D_) + c8*8);
            *(uint4*)(Vs + row*72 + c8*8) =
                *(const uint4*)(Vrow + (size_t)row*S_ + kt*64 + c8*8);
        }
        __syncthreads();

        // ---- S = Q K^T ----
        float acc[8][4];
        #pragma unroll
        for (int ni = 0; ni < 8; ni++)
            #pragma unroll
            for (int r = 0; r < 4; r++) acc[ni][r] = 0.f;

        const uint32_t* Ku = (const uint32_t*)Ks;
        #pragma unroll
        for (int kk = 0; kk < 4; kk++) {
            #pragma unroll
            for (int ni = 0; ni < 8; ni++) {
                uint32_t bf[2];
                const int base = (ni*8 + g)*SWW + kk*8 + tg;
                bf[0] = Ku[base];
                bf[1] = Ku[base + 4];
                mma_f16(acc[ni], aQ[kk], bf);
            }
        }

        // ---- online softmax (rows g, g+8 of warp slice) ----
        #pragma unroll
        for (int ni = 0; ni < 8; ni++)
            #pragma unroll
            for (int r = 0; r < 4; r++) acc[ni][r] *= 0.125f;

        float tm0 = -1e30f, tm1 = -1e30f;
        #pragma unroll
        for (int ni = 0; ni < 8; ni++) {
            tm0 = fmaxf(tm0, fmaxf(acc[ni][0], acc[ni][1]));
            tm1 = fmaxf(tm1, fmaxf(acc[ni][2], acc[ni][3]));
        }
        #pragma unroll
        for (int off = 1; off < 4; off <<= 1) {
            tm0 = fmaxf(tm0, __shfl_xor_sync(0xffffffffu, tm0, off));
            tm1 = fmaxf(tm1, __shfl_xor_sync(0xffffffffu, tm1, off));
        }
        const float mn0 = fmaxf(m[0], tm0);
        const float mn1 = fmaxf(m[1], tm1);
        const float corr0 = __expf(m[0] - mn0);
        const float corr1 = __expf(m[1] - mn1);
        float ts0 = 0.f, ts1 = 0.f;
        #pragma unroll
        for (int ni = 0; ni < 8; ni++) {
            acc[ni][0] = __expf(acc[ni][0] - mn0);
            acc[ni][1] = __expf(acc[ni][1] - mn0);
            acc[ni][2] = __expf(acc[ni][2] - mn1);
            acc[ni][3] = __expf(acc[ni][3] - mn1);
            ts0 += acc[ni][0] + acc[ni][1];
            ts1 += acc[ni][2] + acc[ni][3];
        }
        #pragma unroll
        for (int off = 1; off < 4; off <<= 1) {
            ts0 += __shfl_xor_sync(0xffffffffu, ts0, off);
            ts1 += __shfl_xor_sync(0xffffffffu, ts1, off);
        }
        l[0] = l[0]*corr0 + ts0;  m[0] = mn0;
        l[1] = l[1]*corr1 + ts1;  m[1] = mn1;
        #pragma unroll
        for (int ni = 0; ni < 8; ni++) {
            o[ni][0] *= corr0; o[ni][1] *= corr0;
            o[ni][2] *= corr1; o[ni][3] *= corr1;
        }

        // ---- store P (half) to warp-private smem slice ----
        {
            uint32_t* Psu = (uint32_t*)Ps;
            #pragma unroll
            for (int ni = 0; ni < 8; ni++) {
                Psu[(wq*16 + g    )*SWW + ni*4 + tg] = f2h2(acc[ni][0], acc[ni][1]);
                Psu[(wq*16 + g + 8)*SWW + ni*4 + tg] = f2h2(acc[ni][2], acc[ni][3]);
            }
        }
        __syncwarp();

        // ---- O += P V ----
        const uint32_t* Pu = (const uint32_t*)Ps;
        const uint32_t* Vu = (const uint32_t*)Vs;
        #pragma unroll
        for (int kk = 0; kk < 4; kk++) {
            uint32_t aP[4];
            const int pbase = (wq*16 + g)*SWW + kk*8 + tg;
            aP[0] = Pu[pbase];
            aP[1] = Pu[pbase + 8*SWW];
            aP[2] = Pu[pbase + 4];
            aP[3] = Pu[pbase + 8*SWW + 4];
            #pragma unroll
            for (int ni = 0; ni < 8; ni++) {
                uint32_t bf[2];
                const int vbase = (ni*8 + g)*SWW + kk*8 + tg;
                bf[0] = Vu[vbase];
                bf[1] = Vu[vbase + 4];
                mma_f16(o[ni], aP, bf);
            }
        }
    }

    // ---- epilogue: O /= l, write half ctx ----
    const float inv0 = 1.0f / l[0];
    const float inv1 = 1.0f / l[1];
    const size_t row0 = (size_t)(b*S_ + qt*128 + wq*16 + g);
    const size_t row1 = row0 + 8;
    #pragma unroll
    for (int ni = 0; ni < 8; ni++) {
        const int col = ni*8 + 2*tg;
        *(__half2*)&O[row0*D_ + h*DH_ + col] = __floats2half2_rn(o[ni][0]*inv0, o[ni][1]*inv0);
        *(__half2*)&O[row1*D_ + h*DH_ + col] = __floats2half2_rn(o[ni][2]*inv1, o[ni][3]*inv1);
    }
}

// ---------------- host launcher ----------------
extern "C" void kernel_launch(void* const* d_in, const int* in_sizes, int n_in,
                              void* d_out, int out_size) {
    const float* fx  = (const float*)d_in[0];
    const float* px  = (const float*)d_in[1];
    const float* Wq  = (const float*)d_in[2];
    const float* bq  = (const float*)d_in[3];
    const float* Wk  = (const float*)d_in[4];
    const float* bk  = (const float*)d_in[5];
    const float* Wv  = (const float*)d_in[6];
    const float* bv  = (const float*)d_in[7];
    const float* Wo  = (const float*)d_in[8];
    const float* bo  = (const float*)d_in[9];
    const float* a1  = (const float*)d_in[10];
    const float* be1 = (const float*)d_in[11];
    const float* a2  = (const float*)d_in[12];
    const float* be2 = (const float*)d_in[13];
    const float* W1  = (const float*)d_in[14];
    const float* b1  = (const float*)d_in[15];
    const float* W2  = (const float*)d_in[16];
    const float* b2  = (const float*)d_in[17];
    const float* Wp  = (const float*)d_in[18];
    const float* bp  = (const float*)d_in[19];

    float* xo = (float*)d_out;                    // x: M_ x D_
    float* po = xo + (size_t)M_ * D_;             // p: M_ x P_

    float  *xn, *bqkv;
    __half *xnr, *qkv, *vt, *ctx, *x2h, *hbh, *xrh, *pxh;
    __half *wqkvT, *woT, *w1T, *w2T, *wpT;
    cudaGetSymbolAddress((void**)&xn,    g_xn);
    cudaGetSymbolAddress((void**)&xnr,   g_xnr);
    cudaGetSymbolAddress((void**)&qkv,   g_qkv);
    cudaGetSymbolAddress((void**)&vt,    g_vt);
    cudaGetSymbolAddress((void**)&ctx,   g_ctx);
    cudaGetSymbolAddress((void**)&x2h,   g_x2);
    cudaGetSymbolAddress((void**)&hbh,   g_hb);
    cudaGetSymbolAddress((void**)&xrh,   g_xr);
    cudaGetSymbolAddress((void**)&pxh,   g_pxh);
    cudaGetSymbolAddress((void**)&wqkvT, g_wqkvT);
    cudaGetSymbolAddress((void**)&woT,   g_woT);
    cudaGetSymbolAddress((void**)&w1T,   g_w1T);
    cudaGetSymbolAddress((void**)&w2T,   g_w2T);
    cudaGetSymbolAddress((void**)&wpT,   g_wpT);
    cudaGetSymbolAddress((void**)&bqkv,  g_bqkv);

    cudaFuncSetAttribute(attn_kernel, cudaFuncAttributeMaxDynamicSharedMemorySize, ATTN_SMEM);
    cudaFuncSetAttribute(hgemm<false,true,false>, cudaFuncAttributeMaxDynamicSharedMemorySize, GEMM_SMEM);
    cudaFuncSetAttribute(hgemm<false,true,true>,  cudaFuncAttributeMaxDynamicSharedMemorySize, GEMM_SMEM);
    cudaFuncSetAttribute(hgemm<true,true,false>,  cudaFuncAttributeMaxDynamicSharedMemorySize, GEMM_SMEM);

    // 0. weight transposes + conversions
    dim3 tb(32, 8);
    wtrans_kernel<<<dim3(D_/32, D_/32), tb>>>(Wq, wqkvT,            D_, D_);
    wtrans_kernel<<<dim3(D_/32, D_/32), tb>>>(Wk, wqkvT + D_*D_,    D_, D_);
    wtrans_kernel<<<dim3(D_/32, D_/32), tb>>>(Wv, wqkvT + 2*D_*D_,  D_, D_);
    wtrans_kernel<<<dim3(D_/32, D_/32), tb>>>(Wo, woT, D_, D_);
    wtrans_kernel<<<dim3(DFF_/32, D_/32), tb>>>(W1, w1T, D_, DFF_);
    wtrans_kernel<<<dim3(D_/32, DFF_/32), tb>>>(W2, w2T, DFF_, D_);
    wtrans_kernel<<<dim3(P_/32, (D_+P_)/32), tb>>>(Wp, wpT, D_+P_, P_);
    bcat_kernel<<<(3*D_)/256, 256>>>(bq, bk, bv, bqkv);
    hconv_kernel<<<(M_*P_)/1024, 256>>>(px, pxh, M_*P_);

    // 1. xn = LN1(feature_x): exact -> xn, half -> xnr
    ln_kernel<<<M_, 256>>>(fx, a1, be1, xn, xnr);

    // 2. fused QKV GEMM: [M][3072]
    hgemm<false,true,false><<<dim3(3*D_/128, M_/128), 256, GEMM_SMEM>>>(
        xnr, D_, nullptr, 0, wqkvT, bqkv, nullptr, nullptr, qkv, M_, 3*D_);

    // 2b. transpose V slice for PV mma
    vtrans_kernel<<<dim3(D_/32, S_/32, B_), tb>>>(qkv + 2*D_, vt);

    // 3. attention -> ctx (half)
    attn_kernel<<<dim3(S_/128, H_, B_), 256, ATTN_SMEM>>>(qkv, vt, ctx);

    // 4. x = xn + ctx@Wo + bo (f32 -> d_out)
    dim3 gD(D_/128, M_/128);
    hgemm<false,true,true><<<gD, 256, GEMM_SMEM>>>(
        ctx, D_, nullptr, 0, woT, bo, xn, xo, nullptr, M_, D_);

    // 5. x2 = LN2(x) (half only)
    ln_kernel<<<M_, 256>>>(xo, a2, be2, nullptr, x2h);

    // 6. h = relu(x2@W1+b1) (half); x = x + h@W2 + b2 (f32 -> d_out, half -> xrh)
    hgemm<true,true,false><<<dim3(DFF_/128, M_/128), 256, GEMM_SMEM>>>(
        x2h, D_, nullptr, 0, w1T, b1, nullptr, nullptr, hbh, M_, DFF_);
    hgemm<false,true,true><<<gD, 256, GEMM_SMEM>>>(
        hbh, DFF_, nullptr, 0, w2T, b2, xo, xo, xrh, M_, D_);

    // 7. p = [x, param_x] @ Wp + bp (single dual-A GEMM, K = 1024 + 256)
    hgemm<false,true,false><<<dim3(P_/128, M_/128), 256, GEMM_SMEM>>>(
        xrh, D_, pxh, P_, wpT, bp, nullptr, po, nullptr, M_, P_);
}